// round 8
// baseline (speedup 1.0000x reference)
#include <cuda_runtime.h>
#include <cuda_bf16.h>
#include <cstdint>
#include <math.h>

#define Bn    2048
#define Tn    8
#define CIN   2048
#define CH    1024
#define Mn    32
#define NCLS  21
#define Jn    672
#define EPSv  1e-8f

typedef __nv_bfloat16 bf16;

// ---------------- scratch (device globals) ----------------
// bf16 hi/lo split operands
__device__ __align__(128) bf16 s_xl_hi [Bn * CIN], s_xl_lo [Bn * CIN];
__device__ __align__(128) bf16 s_sfT_hi[Jn * CIN], s_sfT_lo[Jn * CIN];
__device__ __align__(128) bf16 s_Wk_hi [CH * CIN], s_Wk_lo [CH * CIN];
__device__ __align__(128) bf16 s_Wv_hi [CH * CIN], s_Wv_lo [CH * CIN];
__device__ __align__(128) bf16 s_WEk_hi[CH * CIN], s_WEk_lo[CH * CIN];
__device__ __align__(128) bf16 s_WEv_hi[CH * CIN], s_WEv_lo[CH * CIN];
__device__ __align__(128) bf16 s_k_hi  [Bn * CH],  s_k_lo  [Bn * CH];
__device__ __align__(128) bf16 s_Ekn_hi[Jn * CH],  s_Ekn_lo[Jn * CH];
__device__ __align__(128) bf16 s_att_hi[Bn * Jn],  s_att_lo[Bn * Jn];
__device__ __align__(128) bf16 s_EvT_hi[CH * Jn],  s_EvT_lo[CH * Jn];
// fp32 intermediates
__device__ float g_Ek [Jn * CH];
__device__ float g_Ev [Jn * CH];
__device__ float g_q  [Jn];
__device__ float g_k  [Bn * CH];
__device__ float g_v  [Bn * CH];
__device__ float g_ikn[Bn];
__device__ float g_att[Bn * Jn];
__device__ float g_fE [Bn * CH];

// ---------------- split helpers ----------------
__device__ __forceinline__ void split1(bf16* hi, bf16* lo, float v) {
    bf16 h = __float2bfloat16(v);
    *hi = h;
    *lo = __float2bfloat16(v - __bfloat162float(h));
}
__device__ __forceinline__ void split2(bf16* hi, bf16* lo, float x, float y) {
    __nv_bfloat162 h = __floats2bfloat162_rn(x, y);
    __nv_bfloat162 l = __floats2bfloat162_rn(x - __low2float(h), y - __high2float(h));
    *(__nv_bfloat162*)hi = h;
    *(__nv_bfloat162*)lo = l;
}

// ---------------- converters ----------------
// transpose static_feat (n,c,m) -> sfT (n*32+m, c), split
__global__ void transpose_sf(const float* __restrict__ sf) {
    __shared__ float tile[32][33];
    int n  = blockIdx.y;
    int c0 = blockIdx.x * 32;
    tile[threadIdx.y][threadIdx.x] = sf[((size_t)n * CIN + (c0 + threadIdx.y)) * Mn + threadIdx.x];
    __syncthreads();
    size_t o = ((size_t)(n * Mn + threadIdx.y)) * CIN + c0 + threadIdx.x;
    split1(&s_sfT_hi[o], &s_sfT_lo[o], tile[threadIdx.x][threadIdx.y]);
}

struct SplitJob { const float* src; bf16* hi; bf16* lo; };
__global__ void split4(SplitJob j0, SplitJob j1, SplitJob j2, SplitJob j3, int n4) {
    SplitJob j = (blockIdx.z == 0) ? j0 : (blockIdx.z == 1) ? j1 : (blockIdx.z == 2) ? j2 : j3;
    int i = blockIdx.x * blockDim.x + threadIdx.x;
    if (i < n4) {
        float4 v = ((const float4*)j.src)[i];
        split2(j.hi + i * 4,     j.lo + i * 4,     v.x, v.y);
        split2(j.hi + i * 4 + 2, j.lo + i * 4 + 2, v.z, v.w);
    }
}

// xl = x[:, T-1, :], split
__global__ void split_xl(const float* __restrict__ x) {
    int r = blockIdx.x;
    const float4* src = (const float4*)(x + (size_t)r * Tn * CIN + (size_t)(Tn - 1) * CIN);
#pragma unroll
    for (int i = 0; i < 2; i++) {
        int c4 = threadIdx.x + i * 256;
        float4 v = src[c4];
        size_t o = (size_t)r * CIN + c4 * 4;
        split2(&s_xl_hi[o],     &s_xl_lo[o],     v.x, v.y);
        split2(&s_xl_hi[o + 2], &s_xl_lo[o + 2], v.z, v.w);
    }
}

// Ev (j, o) -> EvT (o, j), split
__global__ void evt_split() {
    __shared__ float tile[32][33];
    int j0 = blockIdx.x * 32;  // 21 blocks
    int c0 = blockIdx.y * 32;  // 32 blocks
    tile[threadIdx.y][threadIdx.x] = g_Ev[(size_t)(j0 + threadIdx.y) * CH + c0 + threadIdx.x];
    __syncthreads();
    size_t o = (size_t)(c0 + threadIdx.y) * Jn + j0 + threadIdx.x;
    split1(&s_EvT_hi[o], &s_EvT_lo[o], tile[threadIdx.x][threadIdx.y]);
}

// ---------------- PTX helpers ----------------
__device__ __forceinline__ void ldsm4(uint32_t &r0, uint32_t &r1, uint32_t &r2, uint32_t &r3,
                                      uint32_t addr) {
    asm volatile("ldmatrix.sync.aligned.m8n8.x4.shared.b16 {%0,%1,%2,%3}, [%4];"
                 : "=r"(r0), "=r"(r1), "=r"(r2), "=r"(r3) : "r"(addr));
}
__device__ __forceinline__ void mma16816(float &c0, float &c1, float &c2, float &c3,
                                         uint32_t a0, uint32_t a1, uint32_t a2, uint32_t a3,
                                         uint32_t b0, uint32_t b1) {
    asm volatile("mma.sync.aligned.m16n8k16.row.col.f32.bf16.bf16.f32 "
                 "{%0,%1,%2,%3}, {%4,%5,%6,%7}, {%8,%9}, {%0,%1,%2,%3};"
                 : "+f"(c0), "+f"(c1), "+f"(c2), "+f"(c3)
                 : "r"(a0), "r"(a1), "r"(a2), "r"(a3), "r"(b0), "r"(b1));
}
__device__ __forceinline__ void cpa16(uint32_t dst, const void* src, bool pred) {
    int sz = pred ? 16 : 0;
    asm volatile("cp.async.cg.shared.global [%0], [%1], 16, %2;"
                 :: "r"(dst), "l"(src), "r"(sz));
}
#define CPA_COMMIT() asm volatile("cp.async.commit_group;" ::: "memory")
#define CPA_WAIT1()  asm volatile("cp.async.wait_group 1;" ::: "memory")
#define CPA_WAIT0()  asm volatile("cp.async.wait_group 0;" ::: "memory")

// =====================================================================
// bf16x3 TN GEMM on pre-split operands: C = A @ B^T + bias
// A: [Md][Kd] hi/lo, B: [Nd][Kd] hi/lo (row-major, K-major).
// CTA tile 256x128, warp tile 64x64 (8 warps), KT=32, 3-stage cp.async.
// Requires Kd % 32 == 0.
// =====================================================================
struct GP {
    const bf16 *Ahi, *Alo; int lda;
    const bf16 *Bhi, *Blo; int ldb;
    const float* bias;
    float* C; bf16 *Chi, *Clo; int ldc;
    int Md, Nd, Kd;
};

// per-stage smem layout (bytes): Ahi 0 (256*80), Alo 20480, Bhi 40960 (128*80), Blo 51200
#define STG       61440
#define GEMM_SMEM (3 * STG)

__device__ __forceinline__ void issue_loads(const GP& p, uint32_t sb, int stage,
                                            int bm0, int bn0, int k0, int tid) {
    uint32_t base = sb + stage * STG;
#pragma unroll
    for (int i = 0; i < 4; i++) {            // A: 256 rows x 4 chunks
        int id = tid + i * 256;
        int r = id >> 2, ch = id & 3;
        int gr = bm0 + r;
        bool ok = (gr < p.Md);
        size_t go = (size_t)gr * p.lda + k0 + ch * 8;
        uint32_t d = base + r * 80 + ch * 16;
        cpa16(d,          p.Ahi + go, ok);
        cpa16(d + 20480,  p.Alo + go, ok);
    }
#pragma unroll
    for (int i = 0; i < 2; i++) {            // B: 128 rows x 4 chunks
        int id = tid + i * 256;
        int r = id >> 2, ch = id & 3;
        int gr = bn0 + r;
        bool ok = (gr < p.Nd);
        size_t go = (size_t)gr * p.ldb + k0 + ch * 8;
        uint32_t d = base + 40960 + r * 80 + ch * 16;
        cpa16(d,          p.Bhi + go, ok);
        cpa16(d + 10240,  p.Blo + go, ok);
    }
    CPA_COMMIT();
}

__device__ void gemm_core(const GP& p, char* smem, int bm0, int bn0) {
    const uint32_t sb = (uint32_t)__cvta_generic_to_shared(smem);
    const int tid  = threadIdx.x;
    const int lane = tid & 31;
    const int warp = tid >> 5;
    const int wm0 = (warp >> 1) * 64;   // 0..192
    const int wn0 = (warp & 1) * 64;    // 0,64

    float acc[4][8][4];
#pragma unroll
    for (int i = 0; i < 4; i++)
#pragma unroll
        for (int j = 0; j < 8; j++) {
            acc[i][j][0] = 0.f; acc[i][j][1] = 0.f; acc[i][j][2] = 0.f; acc[i][j][3] = 0.f;
        }

    const int nk = p.Kd >> 5;
    issue_loads(p, sb, 0, bm0, bn0, 0, tid);
    if (nk > 1) issue_loads(p, sb, 1, bm0, bn0, 32, tid);

    for (int it = 0; it < nk; it++) {
        if (it + 1 < nk) CPA_WAIT1(); else CPA_WAIT0();
        __syncthreads();

        if (it + 2 < nk) issue_loads(p, sb, (it + 2) % 3, bm0, bn0, (it + 2) << 5, tid);

        const uint32_t base = sb + (it % 3) * STG;
#pragma unroll
        for (int kk = 0; kk < 32; kk += 16) {
            uint32_t Ah[4][4], Al[4][4];
#pragma unroll
            for (int mt = 0; mt < 4; mt++) {
                uint32_t ao = base + (uint32_t)((wm0 + mt * 16 + (lane & 15)) * 80
                              + (kk + ((lane >> 4) << 3)) * 2);
                ldsm4(Ah[mt][0], Ah[mt][1], Ah[mt][2], Ah[mt][3], ao);
                ldsm4(Al[mt][0], Al[mt][1], Al[mt][2], Al[mt][3], ao + 20480u);
            }
#pragma unroll
            for (int ntp = 0; ntp < 4; ntp++) {
                uint32_t bh0, bh1, bh2, bh3, bl0, bl1, bl2, bl3;
                uint32_t bo = base + 40960u + (uint32_t)((wn0 + ntp * 16 + (lane & 15)) * 80
                              + (kk + ((lane >> 4) << 3)) * 2);
                ldsm4(bh0, bh1, bh2, bh3, bo);
                ldsm4(bl0, bl1, bl2, bl3, bo + 10240u);
#pragma unroll
                for (int mt = 0; mt < 4; mt++) {
                    float* c0 = acc[mt][2 * ntp];
                    float* c1 = acc[mt][2 * ntp + 1];
                    mma16816(c0[0], c0[1], c0[2], c0[3],
                             Ah[mt][0], Ah[mt][1], Ah[mt][2], Ah[mt][3], bh0, bh2);
                    mma16816(c0[0], c0[1], c0[2], c0[3],
                             Ah[mt][0], Ah[mt][1], Ah[mt][2], Ah[mt][3], bl0, bl2);
                    mma16816(c0[0], c0[1], c0[2], c0[3],
                             Al[mt][0], Al[mt][1], Al[mt][2], Al[mt][3], bh0, bh2);
                    mma16816(c1[0], c1[1], c1[2], c1[3],
                             Ah[mt][0], Ah[mt][1], Ah[mt][2], Ah[mt][3], bh1, bh3);
                    mma16816(c1[0], c1[1], c1[2], c1[3],
                             Ah[mt][0], Ah[mt][1], Ah[mt][2], Ah[mt][3], bl1, bl3);
                    mma16816(c1[0], c1[1], c1[2], c1[3],
                             Al[mt][0], Al[mt][1], Al[mt][2], Al[mt][3], bh1, bh3);
                }
            }
        }
        __syncthreads();
    }

    // epilogue
#pragma unroll
    for (int mt = 0; mt < 4; mt++)
#pragma unroll
        for (int nt = 0; nt < 8; nt++) {
            int r0 = bm0 + wm0 + mt * 16 + (lane >> 2);
            int cc = bn0 + wn0 + nt * 8 + ((lane & 3) << 1);
            if (cc < p.Nd) {
                float b0 = p.bias ? p.bias[cc]     : 0.f;
                float b1 = p.bias ? p.bias[cc + 1] : 0.f;
                if (r0 < p.Md) {
                    float x0 = acc[mt][nt][0] + b0, x1 = acc[mt][nt][1] + b1;
                    *(float2*)&p.C[(size_t)r0 * p.ldc + cc] = make_float2(x0, x1);
                    if (p.Chi) split2(&p.Chi[(size_t)r0 * p.ldc + cc],
                                      &p.Clo[(size_t)r0 * p.ldc + cc], x0, x1);
                }
                if (r0 + 8 < p.Md) {
                    float x2 = acc[mt][nt][2] + b0, x3 = acc[mt][nt][3] + b1;
                    *(float2*)&p.C[(size_t)(r0 + 8) * p.ldc + cc] = make_float2(x2, x3);
                    if (p.Chi) split2(&p.Chi[(size_t)(r0 + 8) * p.ldc + cc],
                                      &p.Clo[(size_t)(r0 + 8) * p.ldc + cc], x2, x3);
                }
            }
        }
}

// front: by<8 -> xl part (k/v), by>=8 -> sfT part (Ek/Ev); z selects pair
__global__ __launch_bounds__(256) void front_gemm(GP xk, GP xv, GP sk, GP sv) {
    extern __shared__ char dsm[];
    int by = blockIdx.y;
    GP p;
    int bm0;
    if (by < 8) { p = blockIdx.z ? xv : xk; bm0 = by * 256; }
    else        { p = blockIdx.z ? sv : sk; bm0 = (by - 8) * 256; }
    gemm_core(p, dsm, bm0, blockIdx.x * 128);
}
__global__ __launch_bounds__(256) void one_gemm(GP p) {
    extern __shared__ char dsm[];
    gemm_core(p, dsm, blockIdx.y * 256, blockIdx.x * 128);
}

// ---------------- normalize Ek rows -> Ekn hi/lo; q[j] = Ev[j,:].Ww ----------------
__global__ void prep_rows(const float* __restrict__ Ww) {
    int j = blockIdx.x;
    const float* ek = g_Ek + (size_t)j * CH;
    const float* ev = g_Ev + (size_t)j * CH;
    float ss = 0.f, dq = 0.f;
    for (int o = threadIdx.x; o < CH; o += 256) {
        float e = ek[o];
        ss += e * e;
        dq += ev[o] * Ww[o];
    }
#pragma unroll
    for (int off = 16; off; off >>= 1) {
        ss += __shfl_xor_sync(0xffffffffu, ss, off);
        dq += __shfl_xor_sync(0xffffffffu, dq, off);
    }
    __shared__ float s1[8], s2[8];
    int lane = threadIdx.x & 31, w = threadIdx.x >> 5;
    if (lane == 0) { s1[w] = ss; s2[w] = dq; }
    __syncthreads();
    if (threadIdx.x == 0) {
        float a = 0.f, q = 0.f;
        for (int i = 0; i < 8; i++) { a += s1[i]; q += s2[i]; }
        s1[0] = 1.f / fmaxf(sqrtf(a), EPSv);
        g_q[j] = q;
    }
    __syncthreads();
    float inv = s1[0];
    for (int o = threadIdx.x; o < CH; o += 256) {
        size_t idx = (size_t)j * CH + o;
        split1(&s_Ekn_hi[idx], &s_Ekn_lo[idx], ek[o] * inv);
    }
}

// ---------------- 1/||k[b]|| ----------------
__global__ void knorm_kernel() {
    int b = blockIdx.x;
    const float* kr = g_k + (size_t)b * CH;
    float ss = 0.f;
    for (int o = threadIdx.x; o < CH; o += 256) { float t = kr[o]; ss += t * t; }
#pragma unroll
    for (int off = 16; off; off >>= 1) ss += __shfl_xor_sync(0xffffffffu, ss, off);
    __shared__ float s1[8];
    int lane = threadIdx.x & 31, w = threadIdx.x >> 5;
    if (lane == 0) s1[w] = ss;
    __syncthreads();
    if (threadIdx.x == 0) {
        float a = 0.f;
        for (int i = 0; i < 8; i++) a += s1[i];
        g_ikn[b] = 1.f / fmaxf(sqrtf(a), EPSv);
    }
}

// ---------------- attention: softmax_m, logits via q, softmax_n, g=fw*w (split) ----------------
__global__ void attn_kernel(const float* __restrict__ bw) {
    int b = blockIdx.x;
    int m = threadIdx.x;
    int n = threadIdx.y;
    int j = n * Mn + m;
    float inv = g_ikn[b];
    float c = g_att[(size_t)b * Jn + j] * inv;

    float mx = c;
#pragma unroll
    for (int off = 16; off; off >>= 1) mx = fmaxf(mx, __shfl_xor_sync(0xffffffffu, mx, off));
    float e = __expf(c - mx);
    float s = e;
#pragma unroll
    for (int off = 16; off; off >>= 1) s += __shfl_xor_sync(0xffffffffu, s, off);
    float w = e / s;

    float lq = w * g_q[j];
#pragma unroll
    for (int off = 16; off; off >>= 1) lq += __shfl_xor_sync(0xffffffffu, lq, off);

    __shared__ float sl[NCLS];
    if (m == 0) sl[n] = lq + bw[0];
    __syncthreads();

    float fmx = -1e30f;
#pragma unroll
    for (int i = 0; i < NCLS; i++) fmx = fmaxf(fmx, sl[i]);
    float fs = 0.f;
#pragma unroll
    for (int i = 0; i < NCLS; i++) fs += __expf(sl[i] - fmx);
    float fw = __expf(sl[n] - fmx) / fs;

    size_t idx = (size_t)b * Jn + j;
    split1(&s_att_hi[idx], &s_att_lo[idx], fw * w);
}

// ---------------- final: out = relu([v, fE]) @ Wout^T + bout (8 rows/block) ----------------
__global__ void out_kernel(const float* __restrict__ Wout, const float* __restrict__ bout,
                           float* __restrict__ out) {
    __shared__ float sh[8][NCLS];
    int lane = threadIdx.x & 31, w = threadIdx.x >> 5;
    for (int bb = 0; bb < 8; bb++) {
        int b = blockIdx.x * 8 + bb;
        const float* vr = g_v  + (size_t)b * CH;
        const float* fr = g_fE + (size_t)b * CH;
        float acc[NCLS];
#pragma unroll
        for (int c = 0; c < NCLS; c++) acc[c] = 0.f;
        for (int o = threadIdx.x; o < CH; o += 256) {
            float rv = fmaxf(vr[o], 0.f);
            float rf = fmaxf(fr[o], 0.f);
#pragma unroll
            for (int c = 0; c < NCLS; c++)
                acc[c] += rv * Wout[(size_t)c * (2 * CH) + o] + rf * Wout[(size_t)c * (2 * CH) + CH + o];
        }
#pragma unroll
        for (int c = 0; c < NCLS; c++) {
            float vsum = acc[c];
#pragma unroll
            for (int off = 16; off; off >>= 1) vsum += __shfl_xor_sync(0xffffffffu, vsum, off);
            if (lane == 0) sh[w][c] = vsum;
        }
        __syncthreads();
        if (threadIdx.x < NCLS) {
            float s = 0.f;
            for (int wi = 0; wi < 8; wi++) s += sh[wi][threadIdx.x];
            out[(size_t)b * NCLS + threadIdx.x] = s + bout[threadIdx.x];
        }
        __syncthreads();
    }
}

// ---------------- host launcher ----------------
extern "C" void kernel_launch(void* const* d_in, const int* in_sizes, int n_in,
                              void* d_out, int out_size) {
    const float* x    = (const float*)d_in[0];
    const float* sf   = (const float*)d_in[1];
    const float* Wk   = (const float*)d_in[2];
    const float* bk   = (const float*)d_in[3];
    const float* Wv   = (const float*)d_in[4];
    const float* bv   = (const float*)d_in[5];
    const float* WEk  = (const float*)d_in[6];
    const float* bEk  = (const float*)d_in[7];
    const float* WEv  = (const float*)d_in[8];
    const float* bEv  = (const float*)d_in[9];
    const float* Ww   = (const float*)d_in[10];
    const float* bw   = (const float*)d_in[11];
    const float* Wout = (const float*)d_in[12];
    const float* bout = (const float*)d_in[13];
    float* out = (float*)d_out;

    // symbol addresses
    bf16 *xl_hi, *xl_lo, *sfT_hi, *sfT_lo, *Wk_hi, *Wk_lo, *Wv_hi, *Wv_lo;
    bf16 *WEk_hi, *WEk_lo, *WEv_hi, *WEv_lo, *k_hi, *k_lo, *Ekn_hi, *Ekn_lo;
    bf16 *att_hi, *att_lo, *EvT_hi, *EvT_lo;
    float *p_Ek, *p_Ev, *p_k, *p_v, *p_att, *p_fE;
    cudaGetSymbolAddress((void**)&xl_hi,  s_xl_hi);  cudaGetSymbolAddress((void**)&xl_lo,  s_xl_lo);
    cudaGetSymbolAddress((void**)&sfT_hi, s_sfT_hi); cudaGetSymbolAddress((void**)&sfT_lo, s_sfT_lo);
    cudaGetSymbolAddress((void**)&Wk_hi,  s_Wk_hi);  cudaGetSymbolAddress((void**)&Wk_lo,  s_Wk_lo);
    cudaGetSymbolAddress((void**)&Wv_hi,  s_Wv_hi);  cudaGetSymbolAddress((void**)&Wv_lo,  s_Wv_lo);
    cudaGetSymbolAddress((void**)&WEk_hi, s_WEk_hi); cudaGetSymbolAddress((void**)&WEk_lo, s_WEk_lo);
    cudaGetSymbolAddress((void**)&WEv_hi, s_WEv_hi); cudaGetSymbolAddress((void**)&WEv_lo, s_WEv_lo);
    cudaGetSymbolAddress((void**)&k_hi,   s_k_hi);   cudaGetSymbolAddress((void**)&k_lo,   s_k_lo);
    cudaGetSymbolAddress((void**)&Ekn_hi, s_Ekn_hi); cudaGetSymbolAddress((void**)&Ekn_lo, s_Ekn_lo);
    cudaGetSymbolAddress((void**)&att_hi, s_att_hi); cudaGetSymbolAddress((void**)&att_lo, s_att_lo);
    cudaGetSymbolAddress((void**)&EvT_hi, s_EvT_hi); cudaGetSymbolAddress((void**)&EvT_lo, s_EvT_lo);
    cudaGetSymbolAddress((void**)&p_Ek,  g_Ek);
    cudaGetSymbolAddress((void**)&p_Ev,  g_Ev);
    cudaGetSymbolAddress((void**)&p_k,   g_k);
    cudaGetSymbolAddress((void**)&p_v,   g_v);
    cudaGetSymbolAddress((void**)&p_att, g_att);
    cudaGetSymbolAddress((void**)&p_fE,  g_fE);

    static bool attr_done = false;
    if (!attr_done) {
        cudaFuncSetAttribute(front_gemm, cudaFuncAttributeMaxDynamicSharedMemorySize, GEMM_SMEM);
        cudaFuncSetAttribute(one_gemm,   cudaFuncAttributeMaxDynamicSharedMemorySize, GEMM_SMEM);
        attr_done = true;
    }

    // 1) converters
    transpose_sf<<<dim3(CIN / 32, NCLS), dim3(32, 32)>>>(sf);
    {
        SplitJob j0 = {Wk,  Wk_hi,  Wk_lo};
        SplitJob j1 = {Wv,  Wv_hi,  Wv_lo};
        SplitJob j2 = {WEk, WEk_hi, WEk_lo};
        SplitJob j3 = {WEv, WEv_hi, WEv_lo};
        split4<<<dim3((CH * CIN / 4 + 255) / 256, 1, 4), 256>>>(j0, j1, j2, j3, CH * CIN / 4);
    }
    split_xl<<<Bn, 256>>>(x);

    // 2) front GEMMs: k/v (2048x1024,K=2048) + Ek/Ev (672x1024,K=2048), one launch
    {
        GP xk = {xl_hi, xl_lo, CIN, Wk_hi, Wk_lo, CIN, bk, p_k, k_hi, k_lo, CH, Bn, CH, CIN};
        GP xv = {xl_hi, xl_lo, CIN, Wv_hi, Wv_lo, CIN, bv, p_v, nullptr, nullptr, CH, Bn, CH, CIN};
        GP sk = {sfT_hi, sfT_lo, CIN, WEk_hi, WEk_lo, CIN, bEk, p_Ek, nullptr, nullptr, CH, Jn, CH, CIN};
        GP sv = {sfT_hi, sfT_lo, CIN, WEv_hi, WEv_lo, CIN, bEv, p_Ev, nullptr, nullptr, CH, Jn, CH, CIN};
        front_gemm<<<dim3(CH / 128, 11, 2), 256, GEMM_SMEM>>>(xk, xv, sk, sv);
    }

    // 3) prep: Ekn split + q; EvT split; k norms
    prep_rows<<<Jn, 256>>>(Ww);
    evt_split<<<dim3(Jn / 32, CH / 32), dim3(32, 32)>>>();
    knorm_kernel<<<Bn, 256>>>();

    // 4) cos = k @ Ekn^T (2048 x 672, K=1024)
    {
        GP p = {k_hi, k_lo, CH, Ekn_hi, Ekn_lo, CH, nullptr, p_att, nullptr, nullptr, Jn, Bn, Jn, CH};
        one_gemm<<<dim3((Jn + 127) / 128, Bn / 256, 1), 256, GEMM_SMEM>>>(p);
    }

    // 5) softmaxes + g split
    attn_kernel<<<Bn, dim3(32, NCLS)>>>(bw);

    // 6) fE = g @ EvT^T (2048 x 1024, K=672)
    {
        GP p = {att_hi, att_lo, Jn, EvT_hi, EvT_lo, Jn, nullptr, p_fE, nullptr, nullptr, CH, Bn, CH, Jn};
        one_gemm<<<dim3(CH / 128, Bn / 256, 1), 256, GEMM_SMEM>>>(p);
    }

    // 7) output projection
    out_kernel<<<Bn / 8, 256>>>(Wout, bout, out);
}

// round 12
// speedup vs baseline: 1.0456x; 1.0456x over previous
#include <cuda_runtime.h>
#include <cuda_bf16.h>
#include <cstdint>
#include <math.h>

#define Bn    2048
#define Tn    8
#define CIN   2048
#define CH    1024
#define Mn    32
#define NCLS  21
#define Jn    672
#define EPSv  1e-8f

typedef __nv_bfloat16 bf16;

// ---------------- scratch (device globals) ----------------
__device__ __align__(128) bf16 s_xl_hi [Bn * CIN], s_xl_lo [Bn * CIN];
__device__ __align__(128) bf16 s_sfT_hi[Jn * CIN], s_sfT_lo[Jn * CIN];
__device__ __align__(128) bf16 s_Wk_hi [CH * CIN], s_Wk_lo [CH * CIN];
__device__ __align__(128) bf16 s_Wv_hi [CH * CIN], s_Wv_lo [CH * CIN];
__device__ __align__(128) bf16 s_WEk_hi[CH * CIN], s_WEk_lo[CH * CIN];
__device__ __align__(128) bf16 s_WEv_hi[CH * CIN], s_WEv_lo[CH * CIN];
__device__ __align__(128) bf16 s_k_hi  [Bn * CH],  s_k_lo  [Bn * CH];
__device__ __align__(128) bf16 s_Ekn_hi[Jn * CH],  s_Ekn_lo[Jn * CH];
__device__ __align__(128) bf16 s_att_hi[Bn * Jn],  s_att_lo[Bn * Jn];
__device__ __align__(128) bf16 s_EvT_hi[CH * Jn],  s_EvT_lo[CH * Jn];
__device__ float g_Ek [Jn * CH];
__device__ float g_Ev [Jn * CH];
__device__ float g_q  [Jn];
__device__ float g_k  [Bn * CH];
__device__ float g_v  [Bn * CH];
__device__ float g_ikn[Bn];
__device__ float g_att[Bn * Jn];
__device__ float g_fE [Bn * CH];

// ---------------- split helpers ----------------
__device__ __forceinline__ void split1(bf16* hi, bf16* lo, float v) {
    bf16 h = __float2bfloat16(v);
    *hi = h;
    *lo = __float2bfloat16(v - __bfloat162float(h));
}
__device__ __forceinline__ void split2(bf16* hi, bf16* lo, float x, float y) {
    __nv_bfloat162 h = __floats2bfloat162_rn(x, y);
    __nv_bfloat162 l = __floats2bfloat162_rn(x - __low2float(h), y - __high2float(h));
    *(__nv_bfloat162*)hi = h;
    *(__nv_bfloat162*)lo = l;
}

// ---------------- converters ----------------
__global__ void transpose_sf(const float* __restrict__ sf) {
    __shared__ float tile[32][33];
    int n  = blockIdx.y;
    int c0 = blockIdx.x * 32;
    tile[threadIdx.y][threadIdx.x] = sf[((size_t)n * CIN + (c0 + threadIdx.y)) * Mn + threadIdx.x];
    __syncthreads();
    size_t o = ((size_t)(n * Mn + threadIdx.y)) * CIN + c0 + threadIdx.x;
    split1(&s_sfT_hi[o], &s_sfT_lo[o], tile[threadIdx.x][threadIdx.y]);
}

struct SplitJob { const float* src; bf16* hi; bf16* lo; };
__global__ void split4(SplitJob j0, SplitJob j1, SplitJob j2, SplitJob j3, int n4) {
    SplitJob j = (blockIdx.z == 0) ? j0 : (blockIdx.z == 1) ? j1 : (blockIdx.z == 2) ? j2 : j3;
    int i = blockIdx.x * blockDim.x + threadIdx.x;
    if (i < n4) {
        float4 v = ((const float4*)j.src)[i];
        split2(j.hi + i * 4,     j.lo + i * 4,     v.x, v.y);
        split2(j.hi + i * 4 + 2, j.lo + i * 4 + 2, v.z, v.w);
    }
}

__global__ void split_xl(const float* __restrict__ x) {
    int r = blockIdx.x;
    const float4* src = (const float4*)(x + (size_t)r * Tn * CIN + (size_t)(Tn - 1) * CIN);
#pragma unroll
    for (int i = 0; i < 2; i++) {
        int c4 = threadIdx.x + i * 256;
        float4 v = src[c4];
        size_t o = (size_t)r * CIN + c4 * 4;
        split2(&s_xl_hi[o],     &s_xl_lo[o],     v.x, v.y);
        split2(&s_xl_hi[o + 2], &s_xl_lo[o + 2], v.z, v.w);
    }
}

__global__ void evt_split() {
    __shared__ float tile[32][33];
    int j0 = blockIdx.x * 32;
    int c0 = blockIdx.y * 32;
    tile[threadIdx.y][threadIdx.x] = g_Ev[(size_t)(j0 + threadIdx.y) * CH + c0 + threadIdx.x];
    __syncthreads();
    size_t o = (size_t)(c0 + threadIdx.y) * Jn + j0 + threadIdx.x;
    split1(&s_EvT_hi[o], &s_EvT_lo[o], tile[threadIdx.x][threadIdx.y]);
}

// ---------------- PTX helpers ----------------
__device__ __forceinline__ void ldsm4(uint32_t &r0, uint32_t &r1, uint32_t &r2, uint32_t &r3,
                                      uint32_t addr) {
    asm volatile("ldmatrix.sync.aligned.m8n8.x4.shared.b16 {%0,%1,%2,%3}, [%4];"
                 : "=r"(r0), "=r"(r1), "=r"(r2), "=r"(r3) : "r"(addr));
}
__device__ __forceinline__ void mma16816(float &c0, float &c1, float &c2, float &c3,
                                         uint32_t a0, uint32_t a1, uint32_t a2, uint32_t a3,
                                         uint32_t b0, uint32_t b1) {
    asm volatile("mma.sync.aligned.m16n8k16.row.col.f32.bf16.bf16.f32 "
                 "{%0,%1,%2,%3}, {%4,%5,%6,%7}, {%8,%9}, {%0,%1,%2,%3};"
                 : "+f"(c0), "+f"(c1), "+f"(c2), "+f"(c3)
                 : "r"(a0), "r"(a1), "r"(a2), "r"(a3), "r"(b0), "r"(b1));
}
__device__ __forceinline__ void cpa16(uint32_t dst, const void* src, bool pred) {
    int sz = pred ? 16 : 0;
    asm volatile("cp.async.cg.shared.global [%0], [%1], 16, %2;"
                 :: "r"(dst), "l"(src), "r"(sz));
}
#define CPA_COMMIT() asm volatile("cp.async.commit_group;" ::: "memory")
#define CPA_WAIT1()  asm volatile("cp.async.wait_group 1;" ::: "memory")
#define CPA_WAIT0()  asm volatile("cp.async.wait_group 0;" ::: "memory")

// =====================================================================
// bf16x3 TN GEMM, pre-split operands: C = A @ B^T + bias
// CTA tile 256x128, 512 threads, 16 warps (4x4), warp tile 64x32.
// KT=32, 3-stage cp.async. Requires Kd % 32 == 0.
// =====================================================================
struct GP {
    const bf16 *Ahi, *Alo; int lda;
    const bf16 *Bhi, *Blo; int ldb;
    const float* bias;
    float* C; bf16 *Chi, *Clo; int ldc;
    int Md, Nd, Kd;
};

// per-stage layout (bytes): Ahi 0 (256*80), Alo 20480, Bhi 40960 (128*80), Blo 51200
#define STG       61440
#define GEMM_SMEM (3 * STG)

__device__ __forceinline__ void issue_loads(const GP& p, uint32_t sb, int stage,
                                            int bm0, int bn0, int k0, int tid) {
    uint32_t base = sb + stage * STG;
#pragma unroll
    for (int i = 0; i < 2; i++) {            // A: 256 rows x 4 chunks = 1024
        int id = tid + i * 512;
        int r = id >> 2, ch = id & 3;
        int gr = bm0 + r;
        bool ok = (gr < p.Md);
        size_t go = (size_t)gr * p.lda + k0 + ch * 8;
        uint32_t d = base + r * 80 + ch * 16;
        cpa16(d,         p.Ahi + go, ok);
        cpa16(d + 20480, p.Alo + go, ok);
    }
    {                                        // B: 128 rows x 4 chunks = 512
        int r = tid >> 2, ch = tid & 3;
        int gr = bn0 + r;
        bool ok = (gr < p.Nd);
        size_t go = (size_t)gr * p.ldb + k0 + ch * 8;
        uint32_t d = base + 40960 + r * 80 + ch * 16;
        cpa16(d,         p.Bhi + go, ok);
        cpa16(d + 10240, p.Blo + go, ok);
    }
    CPA_COMMIT();
}

__device__ void gemm_core(const GP& p, char* smem, int bm0, int bn0) {
    const uint32_t sb = (uint32_t)__cvta_generic_to_shared(smem);
    const int tid  = threadIdx.x;
    const int lane = tid & 31;
    const int warp = tid >> 5;
    const int wm0 = (warp >> 2) * 64;   // 0,64,128,192
    const int wn0 = (warp & 3) * 32;    // 0,32,64,96

    float acc[4][4][4];
#pragma unroll
    for (int i = 0; i < 4; i++)
#pragma unroll
        for (int j = 0; j < 4; j++) {
            acc[i][j][0] = 0.f; acc[i][j][1] = 0.f; acc[i][j][2] = 0.f; acc[i][j][3] = 0.f;
        }

    const int nk = p.Kd >> 5;
    issue_loads(p, sb, 0, bm0, bn0, 0, tid);
    if (nk > 1) issue_loads(p, sb, 1, bm0, bn0, 32, tid);

    for (int it = 0; it < nk; it++) {
        if (it + 1 < nk) CPA_WAIT1(); else CPA_WAIT0();
        __syncthreads();

        if (it + 2 < nk) issue_loads(p, sb, (it + 2) % 3, bm0, bn0, (it + 2) << 5, tid);

        const uint32_t base = sb + (it % 3) * STG;
#pragma unroll
        for (int kk = 0; kk < 32; kk += 16) {
            // B fragments for full warp n-extent (32): held across mt loop
            uint32_t bhA0, bhA1, bhA2, bhA3, bhB0, bhB1, bhB2, bhB3;
            uint32_t blA0, blA1, blA2, blA3, blB0, blB1, blB2, blB3;
            {
                uint32_t bo = base + 40960u
                    + (uint32_t)((wn0 + (lane & 15)) * 80 + (kk + ((lane >> 4) << 3)) * 2);
                ldsm4(bhA0, bhA1, bhA2, bhA3, bo);
                ldsm4(blA0, blA1, blA2, blA3, bo + 10240u);
                uint32_t bo2 = bo + 16 * 80u;
                ldsm4(bhB0, bhB1, bhB2, bhB3, bo2);
                ldsm4(blB0, blB1, blB2, blB3, bo2 + 10240u);
            }
#pragma unroll
            for (int mt = 0; mt < 4; mt++) {
                uint32_t a0, a1, a2, a3, l0, l1, l2, l3;
                uint32_t ao = base + (uint32_t)((wm0 + mt * 16 + (lane & 15)) * 80
                              + (kk + ((lane >> 4) << 3)) * 2);
                ldsm4(a0, a1, a2, a3, ao);
                ldsm4(l0, l1, l2, l3, ao + 20480u);

                float* c;
                c = acc[mt][0];
                mma16816(c[0], c[1], c[2], c[3], a0, a1, a2, a3, bhA0, bhA2);
                mma16816(c[0], c[1], c[2], c[3], a0, a1, a2, a3, blA0, blA2);
                mma16816(c[0], c[1], c[2], c[3], l0, l1, l2, l3, bhA0, bhA2);
                c = acc[mt][1];
                mma16816(c[0], c[1], c[2], c[3], a0, a1, a2, a3, bhA1, bhA3);
                mma16816(c[0], c[1], c[2], c[3], a0, a1, a2, a3, blA1, blA3);
                mma16816(c[0], c[1], c[2], c[3], l0, l1, l2, l3, bhA1, bhA3);
                c = acc[mt][2];
                mma16816(c[0], c[1], c[2], c[3], a0, a1, a2, a3, bhB0, bhB2);
                mma16816(c[0], c[1], c[2], c[3], a0, a1, a2, a3, blB0, blB2);
                mma16816(c[0], c[1], c[2], c[3], l0, l1, l2, l3, bhB0, bhB2);
                c = acc[mt][3];
                mma16816(c[0], c[1], c[2], c[3], a0, a1, a2, a3, bhB1, bhB3);
                mma16816(c[0], c[1], c[2], c[3], a0, a1, a2, a3, blB1, blB3);
                mma16816(c[0], c[1], c[2], c[3], l0, l1, l2, l3, bhB1, bhB3);
            }
        }
        __syncthreads();
    }

    // epilogue
#pragma unroll
    for (int mt = 0; mt < 4; mt++)
#pragma unroll
        for (int nt = 0; nt < 4; nt++) {
            int r0 = bm0 + wm0 + mt * 16 + (lane >> 2);
            int cc = bn0 + wn0 + nt * 8 + ((lane & 3) << 1);
            if (cc < p.Nd) {
                float b0 = p.bias ? p.bias[cc]     : 0.f;
                float b1 = p.bias ? p.bias[cc + 1] : 0.f;
                if (r0 < p.Md) {
                    float x0 = acc[mt][nt][0] + b0, x1 = acc[mt][nt][1] + b1;
                    *(float2*)&p.C[(size_t)r0 * p.ldc + cc] = make_float2(x0, x1);
                    if (p.Chi) split2(&p.Chi[(size_t)r0 * p.ldc + cc],
                                      &p.Clo[(size_t)r0 * p.ldc + cc], x0, x1);
                }
                if (r0 + 8 < p.Md) {
                    float x2 = acc[mt][nt][2] + b0, x3 = acc[mt][nt][3] + b1;
                    *(float2*)&p.C[(size_t)(r0 + 8) * p.ldc + cc] = make_float2(x2, x3);
                    if (p.Chi) split2(&p.Chi[(size_t)(r0 + 8) * p.ldc + cc],
                                      &p.Clo[(size_t)(r0 + 8) * p.ldc + cc], x2, x3);
                }
            }
        }
}

__global__ __launch_bounds__(512) void front_gemm(GP xk, GP xv, GP sk, GP sv) {
    extern __shared__ char dsm[];
    int by = blockIdx.y;
    GP p;
    int bm0;
    if (by < 8) { p = blockIdx.z ? xv : xk; bm0 = by * 256; }
    else        { p = blockIdx.z ? sv : sk; bm0 = (by - 8) * 256; }
    gemm_core(p, dsm, bm0, blockIdx.x * 128);
}
__global__ __launch_bounds__(512) void one_gemm(GP p) {
    extern __shared__ char dsm[];
    gemm_core(p, dsm, blockIdx.y * 256, blockIdx.x * 128);
}

// ---------------- normalize Ek rows -> Ekn hi/lo; q[j] ----------------
__global__ void prep_rows(const float* __restrict__ Ww) {
    int j = blockIdx.x;
    const float* ek = g_Ek + (size_t)j * CH;
    const float* ev = g_Ev + (size_t)j * CH;
    float ss = 0.f, dq = 0.f;
    for (int o = threadIdx.x; o < CH; o += 256) {
        float e = ek[o];
        ss += e * e;
        dq += ev[o] * Ww[o];
    }
#pragma unroll
    for (int off = 16; off; off >>= 1) {
        ss += __shfl_xor_sync(0xffffffffu, ss, off);
        dq += __shfl_xor_sync(0xffffffffu, dq, off);
    }
    __shared__ float s1[8], s2[8];
    int lane = threadIdx.x & 31, w = threadIdx.x >> 5;
    if (lane == 0) { s1[w] = ss; s2[w] = dq; }
    __syncthreads();
    if (threadIdx.x == 0) {
        float a = 0.f, q = 0.f;
        for (int i = 0; i < 8; i++) { a += s1[i]; q += s2[i]; }
        s1[0] = 1.f / fmaxf(sqrtf(a), EPSv);
        g_q[j] = q;
    }
    __syncthreads();
    float inv = s1[0];
    for (int o = threadIdx.x; o < CH; o += 256) {
        size_t idx = (size_t)j * CH + o;
        split1(&s_Ekn_hi[idx], &s_Ekn_lo[idx], ek[o] * inv);
    }
}

// ---------------- 1/||k[b]|| ----------------
__global__ void knorm_kernel() {
    int b = blockIdx.x;
    const float* kr = g_k + (size_t)b * CH;
    float ss = 0.f;
    for (int o = threadIdx.x; o < CH; o += 256) { float t = kr[o]; ss += t * t; }
#pragma unroll
    for (int off = 16; off; off >>= 1) ss += __shfl_xor_sync(0xffffffffu, ss, off);
    __shared__ float s1[8];
    int lane = threadIdx.x & 31, w = threadIdx.x >> 5;
    if (lane == 0) s1[w] = ss;
    __syncthreads();
    if (threadIdx.x == 0) {
        float a = 0.f;
        for (int i = 0; i < 8; i++) a += s1[i];
        g_ikn[b] = 1.f / fmaxf(sqrtf(a), EPSv);
    }
}

// ---------------- attention ----------------
__global__ void attn_kernel(const float* __restrict__ bw) {
    int b = blockIdx.x;
    int m = threadIdx.x;
    int n = threadIdx.y;
    int j = n * Mn + m;
    float inv = g_ikn[b];
    float c = g_att[(size_t)b * Jn + j] * inv;

    float mx = c;
#pragma unroll
    for (int off = 16; off; off >>= 1) mx = fmaxf(mx, __shfl_xor_sync(0xffffffffu, mx, off));
    float e = __expf(c - mx);
    float s = e;
#pragma unroll
    for (int off = 16; off; off >>= 1) s += __shfl_xor_sync(0xffffffffu, s, off);
    float w = e / s;

    float lq = w * g_q[j];
#pragma unroll
    for (int off = 16; off; off >>= 1) lq += __shfl_xor_sync(0xffffffffu, lq, off);

    __shared__ float sl[NCLS];
    if (m == 0) sl[n] = lq + bw[0];
    __syncthreads();

    float fmx = -1e30f;
#pragma unroll
    for (int i = 0; i < NCLS; i++) fmx = fmaxf(fmx, sl[i]);
    float fs = 0.f;
#pragma unroll
    for (int i = 0; i < NCLS; i++) fs += __expf(sl[i] - fmx);
    float fw = __expf(sl[n] - fmx) / fs;

    size_t idx = (size_t)b * Jn + j;
    split1(&s_att_hi[idx], &s_att_lo[idx], fw * w);
}

// ---------------- output projection (8 rows/block) ----------------
__global__ void out_kernel(const float* __restrict__ Wout, const float* __restrict__ bout,
                           float* __restrict__ out) {
    __shared__ float sh[8][NCLS];
    int lane = threadIdx.x & 31, w = threadIdx.x >> 5;
    for (int bb = 0; bb < 8; bb++) {
        int b = blockIdx.x * 8 + bb;
        const float* vr = g_v  + (size_t)b * CH;
        const float* fr = g_fE + (size_t)b * CH;
        float acc[NCLS];
#pragma unroll
        for (int c = 0; c < NCLS; c++) acc[c] = 0.f;
        for (int o = threadIdx.x; o < CH; o += 256) {
            float rv = fmaxf(vr[o], 0.f);
            float rf = fmaxf(fr[o], 0.f);
#pragma unroll
            for (int c = 0; c < NCLS; c++)
                acc[c] += rv * Wout[(size_t)c * (2 * CH) + o] + rf * Wout[(size_t)c * (2 * CH) + CH + o];
        }
#pragma unroll
        for (int c = 0; c < NCLS; c++) {
            float vsum = acc[c];
#pragma unroll
            for (int off = 16; off; off >>= 1) vsum += __shfl_xor_sync(0xffffffffu, vsum, off);
            if (lane == 0) sh[w][c] = vsum;
        }
        __syncthreads();
        if (threadIdx.x < NCLS) {
            float s = 0.f;
            for (int wi = 0; wi < 8; wi++) s += sh[wi][threadIdx.x];
            out[(size_t)b * NCLS + threadIdx.x] = s + bout[threadIdx.x];
        }
        __syncthreads();
    }
}

// ---------------- host launcher ----------------
extern "C" void kernel_launch(void* const* d_in, const int* in_sizes, int n_in,
                              void* d_out, int out_size) {
    const float* x    = (const float*)d_in[0];
    const float* sf   = (const float*)d_in[1];
    const float* Wk   = (const float*)d_in[2];
    const float* bk   = (const float*)d_in[3];
    const float* Wv   = (const float*)d_in[4];
    const float* bv   = (const float*)d_in[5];
    const float* WEk  = (const float*)d_in[6];
    const float* bEk  = (const float*)d_in[7];
    const float* WEv  = (const float*)d_in[8];
    const float* bEv  = (const float*)d_in[9];
    const float* Ww   = (const float*)d_in[10];
    const float* bw   = (const float*)d_in[11];
    const float* Wout = (const float*)d_in[12];
    const float* bout = (const float*)d_in[13];
    float* out = (float*)d_out;

    bf16 *xl_hi, *xl_lo, *sfT_hi, *sfT_lo, *Wk_hi, *Wk_lo, *Wv_hi, *Wv_lo;
    bf16 *WEk_hi, *WEk_lo, *WEv_hi, *WEv_lo, *k_hi, *k_lo, *Ekn_hi, *Ekn_lo;
    bf16 *att_hi, *att_lo, *EvT_hi, *EvT_lo;
    float *p_Ek, *p_Ev, *p_k, *p_v, *p_att, *p_fE;
    cudaGetSymbolAddress((void**)&xl_hi,  s_xl_hi);  cudaGetSymbolAddress((void**)&xl_lo,  s_xl_lo);
    cudaGetSymbolAddress((void**)&sfT_hi, s_sfT_hi); cudaGetSymbolAddress((void**)&sfT_lo, s_sfT_lo);
    cudaGetSymbolAddress((void**)&Wk_hi,  s_Wk_hi);  cudaGetSymbolAddress((void**)&Wk_lo,  s_Wk_lo);
    cudaGetSymbolAddress((void**)&Wv_hi,  s_Wv_hi);  cudaGetSymbolAddress((void**)&Wv_lo,  s_Wv_lo);
    cudaGetSymbolAddress((void**)&WEk_hi, s_WEk_hi); cudaGetSymbolAddress((void**)&WEk_lo, s_WEk_lo);
    cudaGetSymbolAddress((void**)&WEv_hi, s_WEv_hi); cudaGetSymbolAddress((void**)&WEv_lo, s_WEv_lo);
    cudaGetSymbolAddress((void**)&k_hi,   s_k_hi);   cudaGetSymbolAddress((void**)&k_lo,   s_k_lo);
    cudaGetSymbolAddress((void**)&Ekn_hi, s_Ekn_hi); cudaGetSymbolAddress((void**)&Ekn_lo, s_Ekn_lo);
    cudaGetSymbolAddress((void**)&att_hi, s_att_hi); cudaGetSymbolAddress((void**)&att_lo, s_att_lo);
    cudaGetSymbolAddress((void**)&EvT_hi, s_EvT_hi); cudaGetSymbolAddress((void**)&EvT_lo, s_EvT_lo);
    cudaGetSymbolAddress((void**)&p_Ek,  g_Ek);
    cudaGetSymbolAddress((void**)&p_Ev,  g_Ev);
    cudaGetSymbolAddress((void**)&p_k,   g_k);
    cudaGetSymbolAddress((void**)&p_v,   g_v);
    cudaGetSymbolAddress((void**)&p_att, g_att);
    cudaGetSymbolAddress((void**)&p_fE,  g_fE);

    static bool attr_done = false;
    if (!attr_done) {
        cudaFuncSetAttribute(front_gemm, cudaFuncAttributeMaxDynamicSharedMemorySize, GEMM_SMEM);
        cudaFuncSetAttribute(one_gemm,   cudaFuncAttributeMaxDynamicSharedMemorySize, GEMM_SMEM);
        attr_done = true;
    }

    // 1) converters
    transpose_sf<<<dim3(CIN / 32, NCLS), dim3(32, 32)>>>(sf);
    {
        SplitJob j0 = {Wk,  Wk_hi,  Wk_lo};
        SplitJob j1 = {Wv,  Wv_hi,  Wv_lo};
        SplitJob j2 = {WEk, WEk_hi, WEk_lo};
        SplitJob j3 = {WEv, WEv_hi, WEv_lo};
        split4<<<dim3((CH * CIN / 4 + 255) / 256, 1, 4), 256>>>(j0, j1, j2, j3, CH * CIN / 4);
    }
    split_xl<<<Bn, 256>>>(x);

    // 2) fused front GEMMs
    {
        GP xk = {xl_hi, xl_lo, CIN, Wk_hi, Wk_lo, CIN, bk, p_k, k_hi, k_lo, CH, Bn, CH, CIN};
        GP xv = {xl_hi, xl_lo, CIN, Wv_hi, Wv_lo, CIN, bv, p_v, nullptr, nullptr, CH, Bn, CH, CIN};
        GP sk = {sfT_hi, sfT_lo, CIN, WEk_hi, WEk_lo, CIN, bEk, p_Ek, nullptr, nullptr, CH, Jn, CH, CIN};
        GP sv = {sfT_hi, sfT_lo, CIN, WEv_hi, WEv_lo, CIN, bEv, p_Ev, nullptr, nullptr, CH, Jn, CH, CIN};
        front_gemm<<<dim3(CH / 128, 11, 2), 512, GEMM_SMEM>>>(xk, xv, sk, sv);
    }

    // 3) prep
    prep_rows<<<Jn, 256>>>(Ww);
    evt_split<<<dim3(Jn / 32, CH / 32), dim3(32, 32)>>>();
    knorm_kernel<<<Bn, 256>>>();

    // 4) cos = k @ Ekn^T
    {
        GP p = {k_hi, k_lo, CH, Ekn_hi, Ekn_lo, CH, nullptr, p_att, nullptr, nullptr, Jn, Bn, Jn, CH};
        one_gemm<<<dim3((Jn + 127) / 128, Bn / 256, 1), 512, GEMM_SMEM>>>(p);
    }

    // 5) softmaxes + split
    attn_kernel<<<Bn, dim3(32, NCLS)>>>(bw);

    // 6) fE = g @ EvT^T
    {
        GP p = {att_hi, att_lo, Jn, EvT_hi, EvT_lo, Jn, nullptr, p_fE, nullptr, nullptr, CH, Bn, CH, Jn};
        one_gemm<<<dim3(CH / 128, Bn / 256, 1), 512, GEMM_SMEM>>>(p);
    }

    // 7) output projection
    out_kernel<<<Bn / 8, 256>>>(Wout, bout, out);
}

// round 13
// speedup vs baseline: 1.4019x; 1.3407x over previous
#include <cuda_runtime.h>
#include <cuda_bf16.h>
#include <cstdint>
#include <math.h>

#define Bn    2048
#define Tn    8
#define CIN   2048
#define CH    1024
#define Mn    32
#define NCLS  21
#define Jn    672
#define EPSv  1e-8f

typedef __nv_bfloat16 bf16;

// ---------------- scratch (device globals) ----------------
__device__ __align__(128) bf16 s_xl_hi [Bn * CIN], s_xl_lo [Bn * CIN];
__device__ __align__(128) bf16 s_sfT_hi[Jn * CIN], s_sfT_lo[Jn * CIN];
__device__ __align__(128) bf16 s_Wk_hi [CH * CIN], s_Wk_lo [CH * CIN];
__device__ __align__(128) bf16 s_Wv_hi [CH * CIN], s_Wv_lo [CH * CIN];
__device__ __align__(128) bf16 s_WEk_hi[CH * CIN], s_WEk_lo[CH * CIN];
__device__ __align__(128) bf16 s_WEv_hi[CH * CIN], s_WEv_lo[CH * CIN];
__device__ __align__(128) bf16 s_k_hi  [Bn * CH],  s_k_lo  [Bn * CH];
__device__ __align__(128) bf16 s_Ekn_hi[Jn * CH],  s_Ekn_lo[Jn * CH];
__device__ __align__(128) bf16 s_att_hi[Bn * Jn],  s_att_lo[Bn * Jn];
__device__ __align__(128) bf16 s_EvT_hi[CH * Jn],  s_EvT_lo[CH * Jn];
__device__ float g_Ek [Jn * CH];
__device__ float g_Ev [Jn * CH];
__device__ float g_q  [Jn];
__device__ float g_k  [Bn * CH];
__device__ float g_v  [Bn * CH];
__device__ float g_ikn[Bn];
__device__ float g_att[Bn * Jn];
__device__ float g_fE [Bn * CH];

// ---------------- split helpers ----------------
__device__ __forceinline__ void split1(bf16* hi, bf16* lo, float v) {
    bf16 h = __float2bfloat16(v);
    *hi = h;
    *lo = __float2bfloat16(v - __bfloat162float(h));
}
__device__ __forceinline__ void split2(bf16* hi, bf16* lo, float x, float y) {
    __nv_bfloat162 h = __floats2bfloat162_rn(x, y);
    __nv_bfloat162 l = __floats2bfloat162_rn(x - __low2float(h), y - __high2float(h));
    *(__nv_bfloat162*)hi = h;
    *(__nv_bfloat162*)lo = l;
}

// ---------------- converters ----------------
__global__ void transpose_sf(const float* __restrict__ sf) {
    __shared__ float tile[32][33];
    int n  = blockIdx.y;
    int c0 = blockIdx.x * 32;
    tile[threadIdx.y][threadIdx.x] = sf[((size_t)n * CIN + (c0 + threadIdx.y)) * Mn + threadIdx.x];
    __syncthreads();
    size_t o = ((size_t)(n * Mn + threadIdx.y)) * CIN + c0 + threadIdx.x;
    split1(&s_sfT_hi[o], &s_sfT_lo[o], tile[threadIdx.x][threadIdx.y]);
}

struct SplitJob { const float* src; bf16* hi; bf16* lo; };
__global__ void split4(SplitJob j0, SplitJob j1, SplitJob j2, SplitJob j3, int n4) {
    SplitJob j = (blockIdx.z == 0) ? j0 : (blockIdx.z == 1) ? j1 : (blockIdx.z == 2) ? j2 : j3;
    int i = blockIdx.x * blockDim.x + threadIdx.x;
    if (i < n4) {
        float4 v = ((const float4*)j.src)[i];
        split2(j.hi + i * 4,     j.lo + i * 4,     v.x, v.y);
        split2(j.hi + i * 4 + 2, j.lo + i * 4 + 2, v.z, v.w);
    }
}

__global__ void split_xl(const float* __restrict__ x) {
    int r = blockIdx.x;
    const float4* src = (const float4*)(x + (size_t)r * Tn * CIN + (size_t)(Tn - 1) * CIN);
#pragma unroll
    for (int i = 0; i < 2; i++) {
        int c4 = threadIdx.x + i * 256;
        float4 v = src[c4];
        size_t o = (size_t)r * CIN + c4 * 4;
        split2(&s_xl_hi[o],     &s_xl_lo[o],     v.x, v.y);
        split2(&s_xl_hi[o + 2], &s_xl_lo[o + 2], v.z, v.w);
    }
}

__global__ void evt_split() {
    __shared__ float tile[32][33];
    int j0 = blockIdx.x * 32;
    int c0 = blockIdx.y * 32;
    tile[threadIdx.y][threadIdx.x] = g_Ev[(size_t)(j0 + threadIdx.y) * CH + c0 + threadIdx.x];
    __syncthreads();
    size_t o = (size_t)(c0 + threadIdx.y) * Jn + j0 + threadIdx.x;
    split1(&s_EvT_hi[o], &s_EvT_lo[o], tile[threadIdx.x][threadIdx.y]);
}

// ---------------- PTX helpers ----------------
__device__ __forceinline__ void ldsm4(uint32_t &r0, uint32_t &r1, uint32_t &r2, uint32_t &r3,
                                      uint32_t addr) {
    asm volatile("ldmatrix.sync.aligned.m8n8.x4.shared.b16 {%0,%1,%2,%3}, [%4];"
                 : "=r"(r0), "=r"(r1), "=r"(r2), "=r"(r3) : "r"(addr));
}
__device__ __forceinline__ void mma16816(float &c0, float &c1, float &c2, float &c3,
                                         uint32_t a0, uint32_t a1, uint32_t a2, uint32_t a3,
                                         uint32_t b0, uint32_t b1) {
    asm volatile("mma.sync.aligned.m16n8k16.row.col.f32.bf16.bf16.f32 "
                 "{%0,%1,%2,%3}, {%4,%5,%6,%7}, {%8,%9}, {%0,%1,%2,%3};"
                 : "+f"(c0), "+f"(c1), "+f"(c2), "+f"(c3)
                 : "r"(a0), "r"(a1), "r"(a2), "r"(a3), "r"(b0), "r"(b1));
}
__device__ __forceinline__ void cpa16(uint32_t dst, const void* src, bool pred) {
    int sz = pred ? 16 : 0;
    asm volatile("cp.async.cg.shared.global [%0], [%1], 16, %2;"
                 :: "r"(dst), "l"(src), "r"(sz));
}
#define CPA_COMMIT() asm volatile("cp.async.commit_group;" ::: "memory")
#define CPA_WAIT1()  asm volatile("cp.async.wait_group 1;" ::: "memory")
#define CPA_WAIT0()  asm volatile("cp.async.wait_group 0;" ::: "memory")

// =====================================================================
// bf16x3 TN GEMM, pre-split operands: C = A @ B^T + bias
// CTA tile 128x128, 256 threads, 8 warps (2x4), warp tile 64x32.
// KT=32, 2-stage cp.async, 2 CTAs/SM. Requires Kd % 32 == 0.
// =====================================================================
struct GP {
    const bf16 *Ahi, *Alo; int lda;
    const bf16 *Bhi, *Blo; int ldb;
    const float* bias;
    float* C; bf16 *Chi, *Clo; int ldc;
    int Md, Nd, Kd;
};

// per-stage layout (bytes): Ahi 0 (128*80), Alo 10240, Bhi 20480, Blo 30720
#define STG       40960
#define GEMM_SMEM (2 * STG)

__device__ __forceinline__ void issue_loads(const GP& p, uint32_t sb, int stage,
                                            int bm0, int bn0, int k0, int tid) {
    uint32_t base = sb + stage * STG;
#pragma unroll
    for (int i = 0; i < 2; i++) {            // A: 128 rows x 4 chunks = 512
        int id = tid + i * 256;
        int r = id >> 2, ch = id & 3;
        int gr = bm0 + r;
        bool ok = (gr < p.Md);
        size_t go = (size_t)gr * p.lda + k0 + ch * 8;
        uint32_t d = base + r * 80 + ch * 16;
        cpa16(d,         p.Ahi + go, ok);
        cpa16(d + 10240, p.Alo + go, ok);
    }
#pragma unroll
    for (int i = 0; i < 2; i++) {            // B: 128 rows x 4 chunks = 512
        int id = tid + i * 256;
        int r = id >> 2, ch = id & 3;
        int gr = bn0 + r;
        bool ok = (gr < p.Nd);
        size_t go = (size_t)gr * p.ldb + k0 + ch * 8;
        uint32_t d = base + 20480 + r * 80 + ch * 16;
        cpa16(d,         p.Bhi + go, ok);
        cpa16(d + 10240, p.Blo + go, ok);
    }
    CPA_COMMIT();
}

__device__ void gemm_core(const GP& p, char* smem, int bm0, int bn0) {
    const uint32_t sb = (uint32_t)__cvta_generic_to_shared(smem);
    const int tid  = threadIdx.x;
    const int lane = tid & 31;
    const int warp = tid >> 5;
    const int wm0 = (warp >> 2) * 64;   // 0,64
    const int wn0 = (warp & 3) * 32;    // 0,32,64,96

    float acc[4][4][4];
#pragma unroll
    for (int i = 0; i < 4; i++)
#pragma unroll
        for (int j = 0; j < 4; j++) {
            acc[i][j][0] = 0.f; acc[i][j][1] = 0.f; acc[i][j][2] = 0.f; acc[i][j][3] = 0.f;
        }

    const int nk = p.Kd >> 5;
    issue_loads(p, sb, 0, bm0, bn0, 0, tid);
    if (nk > 1) issue_loads(p, sb, 1, bm0, bn0, 32, tid);

    for (int it = 0; it < nk; it++) {
        if (it + 1 < nk) CPA_WAIT1(); else CPA_WAIT0();
        __syncthreads();

        const uint32_t base = sb + (it & 1) * STG;
#pragma unroll
        for (int kk = 0; kk < 32; kk += 16) {
            // B fragments for full warp n-extent (32), held across mt loop
            uint32_t bhA0, bhA1, bhA2, bhA3, bhB0, bhB1, bhB2, bhB3;
            uint32_t blA0, blA1, blA2, blA3, blB0, blB1, blB2, blB3;
            {
                uint32_t bo = base + 20480u
                    + (uint32_t)((wn0 + (lane & 15)) * 80 + (kk + ((lane >> 4) << 3)) * 2);
                ldsm4(bhA0, bhA1, bhA2, bhA3, bo);
                ldsm4(blA0, blA1, blA2, blA3, bo + 10240u);
                uint32_t bo2 = bo + 16 * 80u;
                ldsm4(bhB0, bhB1, bhB2, bhB3, bo2);
                ldsm4(blB0, blB1, blB2, blB3, bo2 + 10240u);
            }
#pragma unroll
            for (int mt = 0; mt < 4; mt++) {
                uint32_t a0, a1, a2, a3, l0, l1, l2, l3;
                uint32_t ao = base + (uint32_t)((wm0 + mt * 16 + (lane & 15)) * 80
                              + (kk + ((lane >> 4) << 3)) * 2);
                ldsm4(a0, a1, a2, a3, ao);
                ldsm4(l0, l1, l2, l3, ao + 10240u);

                // term-major order: consecutive mma -> different accumulators
                mma16816(acc[mt][0][0], acc[mt][0][1], acc[mt][0][2], acc[mt][0][3],
                         a0, a1, a2, a3, bhA0, bhA2);
                mma16816(acc[mt][1][0], acc[mt][1][1], acc[mt][1][2], acc[mt][1][3],
                         a0, a1, a2, a3, bhA1, bhA3);
                mma16816(acc[mt][2][0], acc[mt][2][1], acc[mt][2][2], acc[mt][2][3],
                         a0, a1, a2, a3, bhB0, bhB2);
                mma16816(acc[mt][3][0], acc[mt][3][1], acc[mt][3][2], acc[mt][3][3],
                         a0, a1, a2, a3, bhB1, bhB3);

                mma16816(acc[mt][0][0], acc[mt][0][1], acc[mt][0][2], acc[mt][0][3],
                         a0, a1, a2, a3, blA0, blA2);
                mma16816(acc[mt][1][0], acc[mt][1][1], acc[mt][1][2], acc[mt][1][3],
                         a0, a1, a2, a3, blA1, blA3);
                mma16816(acc[mt][2][0], acc[mt][2][1], acc[mt][2][2], acc[mt][2][3],
                         a0, a1, a2, a3, blB0, blB2);
                mma16816(acc[mt][3][0], acc[mt][3][1], acc[mt][3][2], acc[mt][3][3],
                         a0, a1, a2, a3, blB1, blB3);

                mma16816(acc[mt][0][0], acc[mt][0][1], acc[mt][0][2], acc[mt][0][3],
                         l0, l1, l2, l3, bhA0, bhA2);
                mma16816(acc[mt][1][0], acc[mt][1][1], acc[mt][1][2], acc[mt][1][3],
                         l0, l1, l2, l3, bhA1, bhA3);
                mma16816(acc[mt][2][0], acc[mt][2][1], acc[mt][2][2], acc[mt][2][3],
                         l0, l1, l2, l3, bhB0, bhB2);
                mma16816(acc[mt][3][0], acc[mt][3][1], acc[mt][3][2], acc[mt][3][3],
                         l0, l1, l2, l3, bhB1, bhB3);
            }
        }
        __syncthreads();
        if (it + 2 < nk) issue_loads(p, sb, it & 1, bm0, bn0, (it + 2) << 5, tid);
    }

    // epilogue
#pragma unroll
    for (int mt = 0; mt < 4; mt++)
#pragma unroll
        for (int nt = 0; nt < 4; nt++) {
            int r0 = bm0 + wm0 + mt * 16 + (lane >> 2);
            int cc = bn0 + wn0 + nt * 8 + ((lane & 3) << 1);
            if (cc < p.Nd) {
                float b0 = p.bias ? p.bias[cc]     : 0.f;
                float b1 = p.bias ? p.bias[cc + 1] : 0.f;
                if (r0 < p.Md) {
                    float x0 = acc[mt][nt][0] + b0, x1 = acc[mt][nt][1] + b1;
                    *(float2*)&p.C[(size_t)r0 * p.ldc + cc] = make_float2(x0, x1);
                    if (p.Chi) split2(&p.Chi[(size_t)r0 * p.ldc + cc],
                                      &p.Clo[(size_t)r0 * p.ldc + cc], x0, x1);
                }
                if (r0 + 8 < p.Md) {
                    float x2 = acc[mt][nt][2] + b0, x3 = acc[mt][nt][3] + b1;
                    *(float2*)&p.C[(size_t)(r0 + 8) * p.ldc + cc] = make_float2(x2, x3);
                    if (p.Chi) split2(&p.Chi[(size_t)(r0 + 8) * p.ldc + cc],
                                      &p.Clo[(size_t)(r0 + 8) * p.ldc + cc], x2, x3);
                }
            }
        }
}

// front: by<16 -> xl part (k/v), by>=16 -> sfT part (Ek/Ev); z selects pair
__global__ __launch_bounds__(256, 2) void front_gemm(GP xk, GP xv, GP sk, GP sv) {
    extern __shared__ char dsm[];
    int by = blockIdx.y;
    GP p;
    int bm0;
    if (by < 16) { p = blockIdx.z ? xv : xk; bm0 = by * 128; }
    else         { p = blockIdx.z ? sv : sk; bm0 = (by - 16) * 128; }
    gemm_core(p, dsm, bm0, blockIdx.x * 128);
}
__global__ __launch_bounds__(256, 2) void one_gemm(GP p) {
    extern __shared__ char dsm[];
    gemm_core(p, dsm, blockIdx.y * 128, blockIdx.x * 128);
}

// ---------------- normalize Ek rows -> Ekn hi/lo; q[j] ----------------
__global__ void prep_rows(const float* __restrict__ Ww) {
    int j = blockIdx.x;
    const float* ek = g_Ek + (size_t)j * CH;
    const float* ev = g_Ev + (size_t)j * CH;
    float ss = 0.f, dq = 0.f;
    for (int o = threadIdx.x; o < CH; o += 256) {
        float e = ek[o];
        ss += e * e;
        dq += ev[o] * Ww[o];
    }
#pragma unroll
    for (int off = 16; off; off >>= 1) {
        ss += __shfl_xor_sync(0xffffffffu, ss, off);
        dq += __shfl_xor_sync(0xffffffffu, dq, off);
    }
    __shared__ float s1[8], s2[8];
    int lane = threadIdx.x & 31, w = threadIdx.x >> 5;
    if (lane == 0) { s1[w] = ss; s2[w] = dq; }
    __syncthreads();
    if (threadIdx.x == 0) {
        float a = 0.f, q = 0.f;
        for (int i = 0; i < 8; i++) { a += s1[i]; q += s2[i]; }
        s1[0] = 1.f / fmaxf(sqrtf(a), EPSv);
        g_q[j] = q;
    }
    __syncthreads();
    float inv = s1[0];
    for (int o = threadIdx.x; o < CH; o += 256) {
        size_t idx = (size_t)j * CH + o;
        split1(&s_Ekn_hi[idx], &s_Ekn_lo[idx], ek[o] * inv);
    }
}

// ---------------- 1/||k[b]|| ----------------
__global__ void knorm_kernel() {
    int b = blockIdx.x;
    const float* kr = g_k + (size_t)b * CH;
    float ss = 0.f;
    for (int o = threadIdx.x; o < CH; o += 256) { float t = kr[o]; ss += t * t; }
#pragma unroll
    for (int off = 16; off; off >>= 1) ss += __shfl_xor_sync(0xffffffffu, ss, off);
    __shared__ float s1[8];
    int lane = threadIdx.x & 31, w = threadIdx.x >> 5;
    if (lane == 0) s1[w] = ss;
    __syncthreads();
    if (threadIdx.x == 0) {
        float a = 0.f;
        for (int i = 0; i < 8; i++) a += s1[i];
        g_ikn[b] = 1.f / fmaxf(sqrtf(a), EPSv);
    }
}

// ---------------- attention ----------------
__global__ void attn_kernel(const float* __restrict__ bw) {
    int b = blockIdx.x;
    int m = threadIdx.x;
    int n = threadIdx.y;
    int j = n * Mn + m;
    float inv = g_ikn[b];
    float c = g_att[(size_t)b * Jn + j] * inv;

    float mx = c;
#pragma unroll
    for (int off = 16; off; off >>= 1) mx = fmaxf(mx, __shfl_xor_sync(0xffffffffu, mx, off));
    float e = __expf(c - mx);
    float s = e;
#pragma unroll
    for (int off = 16; off; off >>= 1) s += __shfl_xor_sync(0xffffffffu, s, off);
    float w = e / s;

    float lq = w * g_q[j];
#pragma unroll
    for (int off = 16; off; off >>= 1) lq += __shfl_xor_sync(0xffffffffu, lq, off);

    __shared__ float sl[NCLS];
    if (m == 0) sl[n] = lq + bw[0];
    __syncthreads();

    float fmx = -1e30f;
#pragma unroll
    for (int i = 0; i < NCLS; i++) fmx = fmaxf(fmx, sl[i]);
    float fs = 0.f;
#pragma unroll
    for (int i = 0; i < NCLS; i++) fs += __expf(sl[i] - fmx);
    float fw = __expf(sl[n] - fmx) / fs;

    size_t idx = (size_t)b * Jn + j;
    split1(&s_att_hi[idx], &s_att_lo[idx], fw * w);
}

// ---------------- output projection (8 rows/block) ----------------
__global__ void out_kernel(const float* __restrict__ Wout, const float* __restrict__ bout,
                           float* __restrict__ out) {
    __shared__ float sh[8][NCLS];
    int lane = threadIdx.x & 31, w = threadIdx.x >> 5;
    for (int bb = 0; bb < 8; bb++) {
        int b = blockIdx.x * 8 + bb;
        const float* vr = g_v  + (size_t)b * CH;
        const float* fr = g_fE + (size_t)b * CH;
        float acc[NCLS];
#pragma unroll
        for (int c = 0; c < NCLS; c++) acc[c] = 0.f;
        for (int o = threadIdx.x; o < CH; o += 256) {
            float rv = fmaxf(vr[o], 0.f);
            float rf = fmaxf(fr[o], 0.f);
#pragma unroll
            for (int c = 0; c < NCLS; c++)
                acc[c] += rv * Wout[(size_t)c * (2 * CH) + o] + rf * Wout[(size_t)c * (2 * CH) + CH + o];
        }
#pragma unroll
        for (int c = 0; c < NCLS; c++) {
            float vsum = acc[c];
#pragma unroll
            for (int off = 16; off; off >>= 1) vsum += __shfl_xor_sync(0xffffffffu, vsum, off);
            if (lane == 0) sh[w][c] = vsum;
        }
        __syncthreads();
        if (threadIdx.x < NCLS) {
            float s = 0.f;
            for (int wi = 0; wi < 8; wi++) s += sh[wi][threadIdx.x];
            out[(size_t)b * NCLS + threadIdx.x] = s + bout[threadIdx.x];
        }
        __syncthreads();
    }
}

// ---------------- host launcher ----------------
extern "C" void kernel_launch(void* const* d_in, const int* in_sizes, int n_in,
                              void* d_out, int out_size) {
    const float* x    = (const float*)d_in[0];
    const float* sf   = (const float*)d_in[1];
    const float* Wk   = (const float*)d_in[2];
    const float* bk   = (const float*)d_in[3];
    const float* Wv   = (const float*)d_in[4];
    const float* bv   = (const float*)d_in[5];
    const float* WEk  = (const float*)d_in[6];
    const float* bEk  = (const float*)d_in[7];
    const float* WEv  = (const float*)d_in[8];
    const float* bEv  = (const float*)d_in[9];
    const float* Ww   = (const float*)d_in[10];
    const float* bw   = (const float*)d_in[11];
    const float* Wout = (const float*)d_in[12];
    const float* bout = (const float*)d_in[13];
    float* out = (float*)d_out;

    bf16 *xl_hi, *xl_lo, *sfT_hi, *sfT_lo, *Wk_hi, *Wk_lo, *Wv_hi, *Wv_lo;
    bf16 *WEk_hi, *WEk_lo, *WEv_hi, *WEv_lo, *k_hi, *k_lo, *Ekn_hi, *Ekn_lo;
    bf16 *att_hi, *att_lo, *EvT_hi, *EvT_lo;
    float *p_Ek, *p_Ev, *p_k, *p_v, *p_att, *p_fE;
    cudaGetSymbolAddress((void**)&xl_hi,  s_xl_hi);  cudaGetSymbolAddress((void**)&xl_lo,  s_xl_lo);
    cudaGetSymbolAddress((void**)&sfT_hi, s_sfT_hi); cudaGetSymbolAddress((void**)&sfT_lo, s_sfT_lo);
    cudaGetSymbolAddress((void**)&Wk_hi,  s_Wk_hi);  cudaGetSymbolAddress((void**)&Wk_lo,  s_Wk_lo);
    cudaGetSymbolAddress((void**)&Wv_hi,  s_Wv_hi);  cudaGetSymbolAddress((void**)&Wv_lo,  s_Wv_lo);
    cudaGetSymbolAddress((void**)&WEk_hi, s_WEk_hi); cudaGetSymbolAddress((void**)&WEk_lo, s_WEk_lo);
    cudaGetSymbolAddress((void**)&WEv_hi, s_WEv_hi); cudaGetSymbolAddress((void**)&WEv_lo, s_WEv_lo);
    cudaGetSymbolAddress((void**)&k_hi,   s_k_hi);   cudaGetSymbolAddress((void**)&k_lo,   s_k_lo);
    cudaGetSymbolAddress((void**)&Ekn_hi, s_Ekn_hi); cudaGetSymbolAddress((void**)&Ekn_lo, s_Ekn_lo);
    cudaGetSymbolAddress((void**)&att_hi, s_att_hi); cudaGetSymbolAddress((void**)&att_lo, s_att_lo);
    cudaGetSymbolAddress((void**)&EvT_hi, s_EvT_hi); cudaGetSymbolAddress((void**)&EvT_lo, s_EvT_lo);
    cudaGetSymbolAddress((void**)&p_Ek,  g_Ek);
    cudaGetSymbolAddress((void**)&p_Ev,  g_Ev);
    cudaGetSymbolAddress((void**)&p_k,   g_k);
    cudaGetSymbolAddress((void**)&p_v,   g_v);
    cudaGetSymbolAddress((void**)&p_att, g_att);
    cudaGetSymbolAddress((void**)&p_fE,  g_fE);

    static bool attr_done = false;
    if (!attr_done) {
        cudaFuncSetAttribute(front_gemm, cudaFuncAttributeMaxDynamicSharedMemorySize, GEMM_SMEM);
        cudaFuncSetAttribute(one_gemm,   cudaFuncAttributeMaxDynamicSharedMemorySize, GEMM_SMEM);
        attr_done = true;
    }

    // 1) converters
    transpose_sf<<<dim3(CIN / 32, NCLS), dim3(32, 32)>>>(sf);
    {
        SplitJob j0 = {Wk,  Wk_hi,  Wk_lo};
        SplitJob j1 = {Wv,  Wv_hi,  Wv_lo};
        SplitJob j2 = {WEk, WEk_hi, WEk_lo};
        SplitJob j3 = {WEv, WEv_hi, WEv_lo};
        split4<<<dim3((CH * CIN / 4 + 255) / 256, 1, 4), 256>>>(j0, j1, j2, j3, CH * CIN / 4);
    }
    split_xl<<<Bn, 256>>>(x);

    // 2) fused front GEMMs: 352 CTAs (1.19 waves at 2 CTA/SM)
    {
        GP xk = {xl_hi, xl_lo, CIN, Wk_hi, Wk_lo, CIN, bk, p_k, k_hi, k_lo, CH, Bn, CH, CIN};
        GP xv = {xl_hi, xl_lo, CIN, Wv_hi, Wv_lo, CIN, bv, p_v, nullptr, nullptr, CH, Bn, CH, CIN};
        GP sk = {sfT_hi, sfT_lo, CIN, WEk_hi, WEk_lo, CIN, bEk, p_Ek, nullptr, nullptr, CH, Jn, CH, CIN};
        GP sv = {sfT_hi, sfT_lo, CIN, WEv_hi, WEv_lo, CIN, bEv, p_Ev, nullptr, nullptr, CH, Jn, CH, CIN};
        front_gemm<<<dim3(CH / 128, 22, 2), 256, GEMM_SMEM>>>(xk, xv, sk, sv);
    }

    // 3) prep
    prep_rows<<<Jn, 256>>>(Ww);
    evt_split<<<dim3(Jn / 32, CH / 32), dim3(32, 32)>>>();
    knorm_kernel<<<Bn, 256>>>();

    // 4) cos = k @ Ekn^T  (96 CTAs, 1 wave)
    {
        GP p = {k_hi, k_lo, CH, Ekn_hi, Ekn_lo, CH, nullptr, p_att, nullptr, nullptr, Jn, Bn, Jn, CH};
        one_gemm<<<dim3((Jn + 127) / 128, Bn / 128, 1), 256, GEMM_SMEM>>>(p);
    }

    // 5) softmaxes + split
    attn_kernel<<<Bn, dim3(32, NCLS)>>>(bw);

    // 6) fE = g @ EvT^T  (128 CTAs, 1 wave)
    {
        GP p = {att_hi, att_lo, Jn, EvT_hi, EvT_lo, Jn, nullptr, p_fE, nullptr, nullptr, CH, Bn, CH, Jn};
        one_gemm<<<dim3(CH / 128, Bn / 128, 1), 256, GEMM_SMEM>>>(p);
    }

    // 7) output projection
    out_kernel<<<Bn / 8, 256>>>(Wout, bout, out);
}

// round 14
// speedup vs baseline: 1.7917x; 1.2780x over previous
#include <cuda_runtime.h>
#include <cuda_fp16.h>
#include <cstdint>
#include <math.h>

#define Bn    2048
#define Tn    8
#define CIN   2048
#define CH    1024
#define Mn    32
#define NCLS  21
#define Jn    672
#define EPSv  1e-8f

typedef __half h16;

// ---------------- scratch (device globals) ----------------
// A-side operands: fp16 hi/lo split (2-term). B-side: single fp16.
__device__ __align__(128) h16 s_xl_hi [Bn * CIN], s_xl_lo [Bn * CIN];
__device__ __align__(128) h16 s_sfT_hi[Jn * CIN], s_sfT_lo[Jn * CIN];
__device__ __align__(128) h16 s_Wk [CH * CIN];
__device__ __align__(128) h16 s_Wv [CH * CIN];
__device__ __align__(128) h16 s_WEk[CH * CIN];
__device__ __align__(128) h16 s_WEv[CH * CIN];
__device__ __align__(128) h16 s_k_hi [Bn * CH], s_k_lo [Bn * CH];
__device__ __align__(128) h16 s_Ekn[Jn * CH];
__device__ __align__(128) h16 s_att_hi[Bn * Jn], s_att_lo[Bn * Jn];
__device__ __align__(128) h16 s_EvT[CH * Jn];
__device__ float g_Ek [Jn * CH];
__device__ float g_Ev [Jn * CH];
__device__ float g_q  [Jn];
__device__ float g_k  [Bn * CH];
__device__ float g_v  [Bn * CH];
__device__ float g_ikn[Bn];
__device__ float g_att[Bn * Jn];
__device__ float g_fE [Bn * CH];

// ---------------- convert helpers ----------------
__device__ __forceinline__ void split1h(h16* hi, h16* lo, float v) {
    h16 h = __float2half_rn(v);
    *hi = h;
    *lo = __float2half_rn(v - __half2float(h));
}
__device__ __forceinline__ void split2h(h16* hi, h16* lo, float x, float y) {
    __half2 h = __floats2half2_rn(x, y);
    __half2 l = __floats2half2_rn(x - __low2float(h), y - __high2float(h));
    *(__half2*)hi = h;
    *(__half2*)lo = l;
}
__device__ __forceinline__ void cvt2h(h16* d, float x, float y) {
    *(__half2*)d = __floats2half2_rn(x, y);
}

// ---------------- converters ----------------
__global__ void transpose_sf(const float* __restrict__ sf) {
    __shared__ float tile[32][33];
    int n  = blockIdx.y;
    int c0 = blockIdx.x * 32;
    tile[threadIdx.y][threadIdx.x] = sf[((size_t)n * CIN + (c0 + threadIdx.y)) * Mn + threadIdx.x];
    __syncthreads();
    size_t o = ((size_t)(n * Mn + threadIdx.y)) * CIN + c0 + threadIdx.x;
    split1h(&s_sfT_hi[o], &s_sfT_lo[o], tile[threadIdx.x][threadIdx.y]);
}

struct CvtJob { const float* src; h16* dst; };
__global__ void convert4(CvtJob j0, CvtJob j1, CvtJob j2, CvtJob j3, int n4) {
    CvtJob j = (blockIdx.z == 0) ? j0 : (blockIdx.z == 1) ? j1 : (blockIdx.z == 2) ? j2 : j3;
    int i = blockIdx.x * blockDim.x + threadIdx.x;
    if (i < n4) {
        float4 v = ((const float4*)j.src)[i];
        cvt2h(j.dst + i * 4,     v.x, v.y);
        cvt2h(j.dst + i * 4 + 2, v.z, v.w);
    }
}

__global__ void split_xl(const float* __restrict__ x) {
    int r = blockIdx.x;
    const float4* src = (const float4*)(x + (size_t)r * Tn * CIN + (size_t)(Tn - 1) * CIN);
#pragma unroll
    for (int i = 0; i < 2; i++) {
        int c4 = threadIdx.x + i * 256;
        float4 v = src[c4];
        size_t o = (size_t)r * CIN + c4 * 4;
        split2h(&s_xl_hi[o],     &s_xl_lo[o],     v.x, v.y);
        split2h(&s_xl_hi[o + 2], &s_xl_lo[o + 2], v.z, v.w);
    }
}

__global__ void evt_split() {
    __shared__ float tile[32][33];
    int j0 = blockIdx.x * 32;
    int c0 = blockIdx.y * 32;
    tile[threadIdx.y][threadIdx.x] = g_Ev[(size_t)(j0 + threadIdx.y) * CH + c0 + threadIdx.x];
    __syncthreads();
    size_t o = (size_t)(c0 + threadIdx.y) * Jn + j0 + threadIdx.x;
    s_EvT[o] = __float2half_rn(tile[threadIdx.x][threadIdx.y]);
}

// ---------------- PTX helpers ----------------
__device__ __forceinline__ void ldsm4(uint32_t &r0, uint32_t &r1, uint32_t &r2, uint32_t &r3,
                                      uint32_t addr) {
    asm volatile("ldmatrix.sync.aligned.m8n8.x4.shared.b16 {%0,%1,%2,%3}, [%4];"
                 : "=r"(r0), "=r"(r1), "=r"(r2), "=r"(r3) : "r"(addr));
}
__device__ __forceinline__ void mma16816h(float &c0, float &c1, float &c2, float &c3,
                                          uint32_t a0, uint32_t a1, uint32_t a2, uint32_t a3,
                                          uint32_t b0, uint32_t b1) {
    asm volatile("mma.sync.aligned.m16n8k16.row.col.f32.f16.f16.f32 "
                 "{%0,%1,%2,%3}, {%4,%5,%6,%7}, {%8,%9}, {%0,%1,%2,%3};"
                 : "+f"(c0), "+f"(c1), "+f"(c2), "+f"(c3)
                 : "r"(a0), "r"(a1), "r"(a2), "r"(a3), "r"(b0), "r"(b1));
}
__device__ __forceinline__ void cpa16(uint32_t dst, const void* src, bool pred) {
    int sz = pred ? 16 : 0;
    asm volatile("cp.async.cg.shared.global [%0], [%1], 16, %2;"
                 :: "r"(dst), "l"(src), "r"(sz));
}
#define CPA_COMMIT() asm volatile("cp.async.commit_group;" ::: "memory")
#define CPA_WAIT1()  asm volatile("cp.async.wait_group 1;" ::: "memory")
#define CPA_WAIT0()  asm volatile("cp.async.wait_group 0;" ::: "memory")

// =====================================================================
// fp16 2-term TN GEMM: C = (Ah+Al) @ B^T + bias
// A: [Md][Kd] fp16 hi/lo, B: [Nd][Kd] single fp16 (row-major, K-major).
// CTA tile 128x128, 256 threads, 8 warps (2x4), warp tile 64x32.
// KT=32, 2-stage cp.async, 2 CTAs/SM, A-frag double-buffer over mt.
// =====================================================================
struct GP {
    const h16 *Ahi, *Alo; int lda;
    const h16 *Bm; int ldb;
    const float* bias;
    float* C; h16 *Chi, *Clo; int ldc;
    int Md, Nd, Kd;
};

// per-stage layout (bytes): Ahi 0 (128*80), Alo 10240, B 20480
#define STG       30720
#define GEMM_SMEM (2 * STG)

__device__ __forceinline__ void issue_loads(const GP& p, uint32_t sb, int stage,
                                            int bm0, int bn0, int k0, int tid) {
    uint32_t base = sb + stage * STG;
#pragma unroll
    for (int i = 0; i < 2; i++) {            // A: 128 rows x 4 chunks = 512
        int id = tid + i * 256;
        int r = id >> 2, ch = id & 3;
        int gr = bm0 + r;
        bool ok = (gr < p.Md);
        size_t go = (size_t)gr * p.lda + k0 + ch * 8;
        uint32_t d = base + r * 80 + ch * 16;
        cpa16(d,         p.Ahi + go, ok);
        cpa16(d + 10240, p.Alo + go, ok);
    }
#pragma unroll
    for (int i = 0; i < 2; i++) {            // B: 128 rows x 4 chunks = 512 (single)
        int id = tid + i * 256;
        int r = id >> 2, ch = id & 3;
        int gr = bn0 + r;
        bool ok = (gr < p.Nd);
        size_t go = (size_t)gr * p.ldb + k0 + ch * 8;
        uint32_t d = base + 20480 + r * 80 + ch * 16;
        cpa16(d, p.Bm + go, ok);
    }
    CPA_COMMIT();
}

__device__ void gemm_core(const GP& p, char* smem, int bm0, int bn0) {
    const uint32_t sb = (uint32_t)__cvta_generic_to_shared(smem);
    const int tid  = threadIdx.x;
    const int lane = tid & 31;
    const int warp = tid >> 5;
    const int wm0 = (warp >> 2) * 64;   // 0,64
    const int wn0 = (warp & 3) * 32;    // 0,32,64,96

    float acc[4][4][4];
#pragma unroll
    for (int i = 0; i < 4; i++)
#pragma unroll
        for (int j = 0; j < 4; j++) {
            acc[i][j][0] = 0.f; acc[i][j][1] = 0.f; acc[i][j][2] = 0.f; acc[i][j][3] = 0.f;
        }

    const int nk = p.Kd >> 5;
    issue_loads(p, sb, 0, bm0, bn0, 0, tid);
    if (nk > 1) issue_loads(p, sb, 1, bm0, bn0, 32, tid);

    for (int it = 0; it < nk; it++) {
        if (it + 1 < nk) CPA_WAIT1(); else CPA_WAIT0();
        __syncthreads();

        const uint32_t base = sb + (it & 1) * STG;
#pragma unroll
        for (int kk = 0; kk < 32; kk += 16) {
            // B fragments (single) for full warp n-extent 32
            uint32_t bA0, bA1, bA2, bA3, bB0, bB1, bB2, bB3;
            {
                uint32_t bo = base + 20480u
                    + (uint32_t)((wn0 + (lane & 15)) * 80 + (kk + ((lane >> 4) << 3)) * 2);
                ldsm4(bA0, bA1, bA2, bA3, bo);
                ldsm4(bB0, bB1, bB2, bB3, bo + 16 * 80u);
            }
            // A fragments double-buffered across mt
            uint32_t Ahf[2][4], Alf[2][4];
            const uint32_t ao0 = base
                + (uint32_t)((wm0 + (lane & 15)) * 80 + (kk + ((lane >> 4) << 3)) * 2);
            ldsm4(Ahf[0][0], Ahf[0][1], Ahf[0][2], Ahf[0][3], ao0);
            ldsm4(Alf[0][0], Alf[0][1], Alf[0][2], Alf[0][3], ao0 + 10240u);
#pragma unroll
            for (int mt = 0; mt < 4; mt++) {
                const int cur = mt & 1, nxt = cur ^ 1;
                if (mt < 3) {
                    uint32_t ao = ao0 + (uint32_t)((mt + 1) * 16 * 80);
                    ldsm4(Ahf[nxt][0], Ahf[nxt][1], Ahf[nxt][2], Ahf[nxt][3], ao);
                    ldsm4(Alf[nxt][0], Alf[nxt][1], Alf[nxt][2], Alf[nxt][3], ao + 10240u);
                }
                // hi-term: 4 independent accumulators
                mma16816h(acc[mt][0][0], acc[mt][0][1], acc[mt][0][2], acc[mt][0][3],
                          Ahf[cur][0], Ahf[cur][1], Ahf[cur][2], Ahf[cur][3], bA0, bA2);
                mma16816h(acc[mt][1][0], acc[mt][1][1], acc[mt][1][2], acc[mt][1][3],
                          Ahf[cur][0], Ahf[cur][1], Ahf[cur][2], Ahf[cur][3], bA1, bA3);
                mma16816h(acc[mt][2][0], acc[mt][2][1], acc[mt][2][2], acc[mt][2][3],
                          Ahf[cur][0], Ahf[cur][1], Ahf[cur][2], Ahf[cur][3], bB0, bB2);
                mma16816h(acc[mt][3][0], acc[mt][3][1], acc[mt][3][2], acc[mt][3][3],
                          Ahf[cur][0], Ahf[cur][1], Ahf[cur][2], Ahf[cur][3], bB1, bB3);
                // lo-term
                mma16816h(acc[mt][0][0], acc[mt][0][1], acc[mt][0][2], acc[mt][0][3],
                          Alf[cur][0], Alf[cur][1], Alf[cur][2], Alf[cur][3], bA0, bA2);
                mma16816h(acc[mt][1][0], acc[mt][1][1], acc[mt][1][2], acc[mt][1][3],
                          Alf[cur][0], Alf[cur][1], Alf[cur][2], Alf[cur][3], bA1, bA3);
                mma16816h(acc[mt][2][0], acc[mt][2][1], acc[mt][2][2], acc[mt][2][3],
                          Alf[cur][0], Alf[cur][1], Alf[cur][2], Alf[cur][3], bB0, bB2);
                mma16816h(acc[mt][3][0], acc[mt][3][1], acc[mt][3][2], acc[mt][3][3],
                          Alf[cur][0], Alf[cur][1], Alf[cur][2], Alf[cur][3], bB1, bB3);
            }
        }
        __syncthreads();
        if (it + 2 < nk) issue_loads(p, sb, it & 1, bm0, bn0, (it + 2) << 5, tid);
    }

    // epilogue
#pragma unroll
    for (int mt = 0; mt < 4; mt++)
#pragma unroll
        for (int nt = 0; nt < 4; nt++) {
            int r0 = bm0 + wm0 + mt * 16 + (lane >> 2);
            int cc = bn0 + wn0 + nt * 8 + ((lane & 3) << 1);
            if (cc < p.Nd) {
                float b0 = p.bias ? p.bias[cc]     : 0.f;
                float b1 = p.bias ? p.bias[cc + 1] : 0.f;
                if (r0 < p.Md) {
                    float x0 = acc[mt][nt][0] + b0, x1 = acc[mt][nt][1] + b1;
                    *(float2*)&p.C[(size_t)r0 * p.ldc + cc] = make_float2(x0, x1);
                    if (p.Chi) split2h(&p.Chi[(size_t)r0 * p.ldc + cc],
                                       &p.Clo[(size_t)r0 * p.ldc + cc], x0, x1);
                }
                if (r0 + 8 < p.Md) {
                    float x2 = acc[mt][nt][2] + b0, x3 = acc[mt][nt][3] + b1;
                    *(float2*)&p.C[(size_t)(r0 + 8) * p.ldc + cc] = make_float2(x2, x3);
                    if (p.Chi) split2h(&p.Chi[(size_t)(r0 + 8) * p.ldc + cc],
                                       &p.Clo[(size_t)(r0 + 8) * p.ldc + cc], x2, x3);
                }
            }
        }
}

// front: by<16 -> xl part (k/v), by>=16 -> sfT part (Ek/Ev); z selects pair
__global__ __launch_bounds__(256, 2) void front_gemm(GP xk, GP xv, GP sk, GP sv) {
    extern __shared__ char dsm[];
    int by = blockIdx.y;
    GP p;
    int bm0;
    if (by < 16) { p = blockIdx.z ? xv : xk; bm0 = by * 128; }
    else         { p = blockIdx.z ? sv : sk; bm0 = (by - 16) * 128; }
    gemm_core(p, dsm, bm0, blockIdx.x * 128);
}
__global__ __launch_bounds__(256, 2) void one_gemm(GP p) {
    extern __shared__ char dsm[];
    gemm_core(p, dsm, blockIdx.y * 128, blockIdx.x * 128);
}

// ---------------- normalize Ek rows -> Ekn (fp16); q[j] ----------------
__global__ void prep_rows(const float* __restrict__ Ww) {
    int j = blockIdx.x;
    const float* ek = g_Ek + (size_t)j * CH;
    const float* ev = g_Ev + (size_t)j * CH;
    float ss = 0.f, dq = 0.f;
    for (int o = threadIdx.x; o < CH; o += 256) {
        float e = ek[o];
        ss += e * e;
        dq += ev[o] * Ww[o];
    }
#pragma unroll
    for (int off = 16; off; off >>= 1) {
        ss += __shfl_xor_sync(0xffffffffu, ss, off);
        dq += __shfl_xor_sync(0xffffffffu, dq, off);
    }
    __shared__ float s1[8], s2[8];
    int lane = threadIdx.x & 31, w = threadIdx.x >> 5;
    if (lane == 0) { s1[w] = ss; s2[w] = dq; }
    __syncthreads();
    if (threadIdx.x == 0) {
        float a = 0.f, q = 0.f;
        for (int i = 0; i < 8; i++) { a += s1[i]; q += s2[i]; }
        s1[0] = 1.f / fmaxf(sqrtf(a), EPSv);
        g_q[j] = q;
    }
    __syncthreads();
    float inv = s1[0];
    for (int o = threadIdx.x; o < CH; o += 256) {
        size_t idx = (size_t)j * CH + o;
        s_Ekn[idx] = __float2half_rn(ek[o] * inv);
    }
}

// ---------------- 1/||k[b]|| ----------------
__global__ void knorm_kernel() {
    int b = blockIdx.x;
    const float* kr = g_k + (size_t)b * CH;
    float ss = 0.f;
    for (int o = threadIdx.x; o < CH; o += 256) { float t = kr[o]; ss += t * t; }
#pragma unroll
    for (int off = 16; off; off >>= 1) ss += __shfl_xor_sync(0xffffffffu, ss, off);
    __shared__ float s1[8];
    int lane = threadIdx.x & 31, w = threadIdx.x >> 5;
    if (lane == 0) s1[w] = ss;
    __syncthreads();
    if (threadIdx.x == 0) {
        float a = 0.f;
        for (int i = 0; i < 8; i++) a += s1[i];
        g_ikn[b] = 1.f / fmaxf(sqrtf(a), EPSv);
    }
}

// ---------------- attention ----------------
__global__ void attn_kernel(const float* __restrict__ bw) {
    int b = blockIdx.x;
    int m = threadIdx.x;
    int n = threadIdx.y;
    int j = n * Mn + m;
    float inv = g_ikn[b];
    float c = g_att[(size_t)b * Jn + j] * inv;

    float mx = c;
#pragma unroll
    for (int off = 16; off; off >>= 1) mx = fmaxf(mx, __shfl_xor_sync(0xffffffffu, mx, off));
    float e = __expf(c - mx);
    float s = e;
#pragma unroll
    for (int off = 16; off; off >>= 1) s += __shfl_xor_sync(0xffffffffu, s, off);
    float w = e / s;

    float lq = w * g_q[j];
#pragma unroll
    for (int off = 16; off; off >>= 1) lq += __shfl_xor_sync(0xffffffffu, lq, off);

    __shared__ float sl[NCLS];
    if (m == 0) sl[n] = lq + bw[0];
    __syncthreads();

    float fmx = -1e30f;
#pragma unroll
    for (int i = 0; i < NCLS; i++) fmx = fmaxf(fmx, sl[i]);
    float fs = 0.f;
#pragma unroll
    for (int i = 0; i < NCLS; i++) fs += __expf(sl[i] - fmx);
    float fw = __expf(sl[n] - fmx) / fs;

    size_t idx = (size_t)b * Jn + j;
    split1h(&s_att_hi[idx], &s_att_lo[idx], fw * w);
}

// ---------------- output projection (8 rows/block) ----------------
__global__ void out_kernel(const float* __restrict__ Wout, const float* __restrict__ bout,
                           float* __restrict__ out) {
    __shared__ float sh[8][NCLS];
    int lane = threadIdx.x & 31, w = threadIdx.x >> 5;
    for (int bb = 0; bb < 8; bb++) {
        int b = blockIdx.x * 8 + bb;
        const float* vr = g_v  + (size_t)b * CH;
        const float* fr = g_fE + (size_t)b * CH;
        float acc[NCLS];
#pragma unroll
        for (int c = 0; c < NCLS; c++) acc[c] = 0.f;
        for (int o = threadIdx.x; o < CH; o += 256) {
            float rv = fmaxf(vr[o], 0.f);
            float rf = fmaxf(fr[o], 0.f);
#pragma unroll
            for (int c = 0; c < NCLS; c++)
                acc[c] += rv * Wout[(size_t)c * (2 * CH) + o] + rf * Wout[(size_t)c * (2 * CH) + CH + o];
        }
#pragma unroll
        for (int c = 0; c < NCLS; c++) {
            float vsum = acc[c];
#pragma unroll
            for (int off = 16; off; off >>= 1) vsum += __shfl_xor_sync(0xffffffffu, vsum, off);
            if (lane == 0) sh[w][c] = vsum;
        }
        __syncthreads();
        if (threadIdx.x < NCLS) {
            float s = 0.f;
            for (int wi = 0; wi < 8; wi++) s += sh[wi][threadIdx.x];
            out[(size_t)b * NCLS + threadIdx.x] = s + bout[threadIdx.x];
        }
        __syncthreads();
    }
}

// ---------------- host launcher ----------------
extern "C" void kernel_launch(void* const* d_in, const int* in_sizes, int n_in,
                              void* d_out, int out_size) {
    const float* x    = (const float*)d_in[0];
    const float* sf   = (const float*)d_in[1];
    const float* Wk   = (const float*)d_in[2];
    const float* bk   = (const float*)d_in[3];
    const float* Wv   = (const float*)d_in[4];
    const float* bv   = (const float*)d_in[5];
    const float* WEk  = (const float*)d_in[6];
    const float* bEk  = (const float*)d_in[7];
    const float* WEv  = (const float*)d_in[8];
    const float* bEv  = (const float*)d_in[9];
    const float* Ww   = (const float*)d_in[10];
    const float* bw   = (const float*)d_in[11];
    const float* Wout = (const float*)d_in[12];
    const float* bout = (const float*)d_in[13];
    float* out = (float*)d_out;

    h16 *xl_hi, *xl_lo, *sfT_hi, *sfT_lo, *pWk, *pWv, *pWEk, *pWEv;
    h16 *k_hi, *k_lo, *Ekn, *att_hi, *att_lo, *EvT;
    float *p_Ek, *p_Ev, *p_k, *p_v, *p_att, *p_fE;
    cudaGetSymbolAddress((void**)&xl_hi,  s_xl_hi);  cudaGetSymbolAddress((void**)&xl_lo,  s_xl_lo);
    cudaGetSymbolAddress((void**)&sfT_hi, s_sfT_hi); cudaGetSymbolAddress((void**)&sfT_lo, s_sfT_lo);
    cudaGetSymbolAddress((void**)&pWk,  s_Wk);
    cudaGetSymbolAddress((void**)&pWv,  s_Wv);
    cudaGetSymbolAddress((void**)&pWEk, s_WEk);
    cudaGetSymbolAddress((void**)&pWEv, s_WEv);
    cudaGetSymbolAddress((void**)&k_hi,   s_k_hi);   cudaGetSymbolAddress((void**)&k_lo,   s_k_lo);
    cudaGetSymbolAddress((void**)&Ekn,    s_Ekn);
    cudaGetSymbolAddress((void**)&att_hi, s_att_hi); cudaGetSymbolAddress((void**)&att_lo, s_att_lo);
    cudaGetSymbolAddress((void**)&EvT,    s_EvT);
    cudaGetSymbolAddress((void**)&p_Ek,  g_Ek);
    cudaGetSymbolAddress((void**)&p_Ev,  g_Ev);
    cudaGetSymbolAddress((void**)&p_k,   g_k);
    cudaGetSymbolAddress((void**)&p_v,   g_v);
    cudaGetSymbolAddress((void**)&p_att, g_att);
    cudaGetSymbolAddress((void**)&p_fE,  g_fE);

    static bool attr_done = false;
    if (!attr_done) {
        cudaFuncSetAttribute(front_gemm, cudaFuncAttributeMaxDynamicSharedMemorySize, GEMM_SMEM);
        cudaFuncSetAttribute(one_gemm,   cudaFuncAttributeMaxDynamicSharedMemorySize, GEMM_SMEM);
        attr_done = true;
    }

    // 1) converters
    transpose_sf<<<dim3(CIN / 32, NCLS), dim3(32, 32)>>>(sf);
    {
        CvtJob j0 = {Wk,  pWk};
        CvtJob j1 = {Wv,  pWv};
        CvtJob j2 = {WEk, pWEk};
        CvtJob j3 = {WEv, pWEv};
        convert4<<<dim3((CH * CIN / 4 + 255) / 256, 1, 4), 256>>>(j0, j1, j2, j3, CH * CIN / 4);
    }
    split_xl<<<Bn, 256>>>(x);

    // 2) fused front GEMMs: 352 CTAs (1.19 waves at 2 CTA/SM)
    {
        GP xk = {xl_hi, xl_lo, CIN, pWk,  CIN, bk,  p_k,  k_hi, k_lo, CH, Bn, CH, CIN};
        GP xv = {xl_hi, xl_lo, CIN, pWv,  CIN, bv,  p_v,  nullptr, nullptr, CH, Bn, CH, CIN};
        GP sk = {sfT_hi, sfT_lo, CIN, pWEk, CIN, bEk, p_Ek, nullptr, nullptr, CH, Jn, CH, CIN};
        GP sv = {sfT_hi, sfT_lo, CIN, pWEv, CIN, bEv, p_Ev, nullptr, nullptr, CH, Jn, CH, CIN};
        front_gemm<<<dim3(CH / 128, 22, 2), 256, GEMM_SMEM>>>(xk, xv, sk, sv);
    }

    // 3) prep
    prep_rows<<<Jn, 256>>>(Ww);
    evt_split<<<dim3(Jn / 32, CH / 32), dim3(32, 32)>>>();
    knorm_kernel<<<Bn, 256>>>();

    // 4) cos = k @ Ekn^T  (96 CTAs)
    {
        GP p = {k_hi, k_lo, CH, Ekn, CH, nullptr, p_att, nullptr, nullptr, Jn, Bn, Jn, CH};
        one_gemm<<<dim3((Jn + 127) / 128, Bn / 128, 1), 256, GEMM_SMEM>>>(p);
    }

    // 5) softmaxes + split
    attn_kernel<<<Bn, dim3(32, NCLS)>>>(bw);

    // 6) fE = g @ EvT^T  (128 CTAs)
    {
        GP p = {att_hi, att_lo, Jn, EvT, Jn, nullptr, p_fE, nullptr, nullptr, CH, Bn, CH, Jn};
        one_gemm<<<dim3(CH / 128, Bn / 128, 1), 256, GEMM_SMEM>>>(p);
    }

    // 7) output projection
    out_kernel<<<Bn / 8, 256>>>(Wout, bout, out);
}

// round 15
// speedup vs baseline: 2.5925x; 1.4470x over previous
#include <cuda_runtime.h>
#include <cuda_fp16.h>
#include <cstdint>
#include <math.h>

#define Bn    2048
#define Tn    8
#define CIN   2048
#define CH    1024
#define Mn    32
#define NCLS  21
#define Jn    672
#define EPSv  1e-8f

typedef __half h16;

// ---------------- scratch (device globals) ----------------
__device__ __align__(128) h16 s_xl [Bn * CIN];
__device__ __align__(128) h16 s_sfT[Jn * CIN];
__device__ __align__(128) h16 s_Wk [CH * CIN];
__device__ __align__(128) h16 s_Wv [CH * CIN];
__device__ __align__(128) h16 s_WEk[CH * CIN];
__device__ __align__(128) h16 s_WEv[CH * CIN];
__device__ __align__(128) h16 s_k  [Bn * CH];
__device__ __align__(128) h16 s_Ekn[Jn * CH];
__device__ __align__(128) h16 s_att[Bn * Jn];
__device__ __align__(128) h16 s_EvT[CH * Jn];
__device__ float g_Ek [Jn * CH];
__device__ float g_Ev [Jn * CH];
__device__ float g_q  [Jn];
__device__ float g_k  [Bn * CH];
__device__ float g_v  [Bn * CH];
__device__ float g_ikn[Bn];
__device__ float g_att[Bn * Jn];
__device__ float g_fE [Bn * CH];

// ---------------- convert helpers ----------------
__device__ __forceinline__ void cvt2h(h16* d, float x, float y) {
    *(__half2*)d = __floats2half2_rn(x, y);
}

// ---------------- converters ----------------
__global__ void transpose_sf(const float* __restrict__ sf) {
    __shared__ float tile[32][33];
    int n  = blockIdx.y;
    int c0 = blockIdx.x * 32;
    tile[threadIdx.y][threadIdx.x] = sf[((size_t)n * CIN + (c0 + threadIdx.y)) * Mn + threadIdx.x];
    __syncthreads();
    size_t o = ((size_t)(n * Mn + threadIdx.y)) * CIN + c0 + threadIdx.x;
    s_sfT[o] = __float2half_rn(tile[threadIdx.x][threadIdx.y]);
}

struct CvtJob { const float* src; h16* dst; };
__global__ void convert4(CvtJob j0, CvtJob j1, CvtJob j2, CvtJob j3, int n4) {
    CvtJob j = (blockIdx.z == 0) ? j0 : (blockIdx.z == 1) ? j1 : (blockIdx.z == 2) ? j2 : j3;
    int i = blockIdx.x * blockDim.x + threadIdx.x;
    if (i < n4) {
        float4 v = ((const float4*)j.src)[i];
        cvt2h(j.dst + i * 4,     v.x, v.y);
        cvt2h(j.dst + i * 4 + 2, v.z, v.w);
    }
}

__global__ void cvt_xl(const float* __restrict__ x) {
    int r = blockIdx.x;
    const float4* src = (const float4*)(x + (size_t)r * Tn * CIN + (size_t)(Tn - 1) * CIN);
#pragma unroll
    for (int i = 0; i < 2; i++) {
        int c4 = threadIdx.x + i * 256;
        float4 v = src[c4];
        size_t o = (size_t)r * CIN + c4 * 4;
        cvt2h(&s_xl[o],     v.x, v.y);
        cvt2h(&s_xl[o + 2], v.z, v.w);
    }
}

__global__ void evt_cvt() {
    __shared__ float tile[32][33];
    int j0 = blockIdx.x * 32;
    int c0 = blockIdx.y * 32;
    tile[threadIdx.y][threadIdx.x] = g_Ev[(size_t)(j0 + threadIdx.y) * CH + c0 + threadIdx.x];
    __syncthreads();
    size_t o = (size_t)(c0 + threadIdx.y) * Jn + j0 + threadIdx.x;
    s_EvT[o] = __float2half_rn(tile[threadIdx.x][threadIdx.y]);
}

// ---------------- PTX helpers ----------------
__device__ __forceinline__ void ldsm4(uint32_t &r0, uint32_t &r1, uint32_t &r2, uint32_t &r3,
                                      uint32_t addr) {
    asm volatile("ldmatrix.sync.aligned.m8n8.x4.shared.b16 {%0,%1,%2,%3}, [%4];"
                 : "=r"(r0), "=r"(r1), "=r"(r2), "=r"(r3) : "r"(addr));
}
__device__ __forceinline__ void mma16816h(float &c0, float &c1, float &c2, float &c3,
                                          uint32_t a0, uint32_t a1, uint32_t a2, uint32_t a3,
                                          uint32_t b0, uint32_t b1) {
    asm volatile("mma.sync.aligned.m16n8k16.row.col.f32.f16.f16.f32 "
                 "{%0,%1,%2,%3}, {%4,%5,%6,%7}, {%8,%9}, {%0,%1,%2,%3};"
                 : "+f"(c0), "+f"(c1), "+f"(c2), "+f"(c3)
                 : "r"(a0), "r"(a1), "r"(a2), "r"(a3), "r"(b0), "r"(b1));
}
__device__ __forceinline__ void cpa16(uint32_t dst, const void* src, bool pred) {
    int sz = pred ? 16 : 0;
    asm volatile("cp.async.cg.shared.global [%0], [%1], 16, %2;"
                 :: "r"(dst), "l"(src), "r"(sz));
}
#define CPA_COMMIT() asm volatile("cp.async.commit_group;" ::: "memory")
#define CPA_WAIT1()  asm volatile("cp.async.wait_group 1;" ::: "memory")
#define CPA_WAIT0()  asm volatile("cp.async.wait_group 0;" ::: "memory")

// =====================================================================
// fp16 TN GEMM: C = A @ B^T + bias   (A: Md x Kd, B: Nd x Kd, fp16)
// CTA tile 128x128, 256 threads, 8 warps (2x4), warp tile 64x32.
// KT=32, 2-stage cp.async, 2 CTAs/SM, A-frag double-buffer over mt.
// =====================================================================
struct GP {
    const h16 *A; int lda;
    const h16 *Bm; int ldb;
    const float* bias;
    float* C; h16 *Ch; int ldc;
    int Md, Nd, Kd;
};

// per-stage layout (bytes): A 0 (128*80), B 10240 (128*80)
#define STG       20480
#define GEMM_SMEM (2 * STG)

__device__ __forceinline__ void issue_loads(const GP& p, uint32_t sb, int stage,
                                            int bm0, int bn0, int k0, int tid) {
    uint32_t base = sb + stage * STG;
#pragma unroll
    for (int i = 0; i < 2; i++) {            // A: 128 rows x 4 chunks = 512
        int id = tid + i * 256;
        int r = id >> 2, ch = id & 3;
        int gr = bm0 + r;
        bool ok = (gr < p.Md);
        size_t go = (size_t)gr * p.lda + k0 + ch * 8;
        cpa16(base + r * 80 + ch * 16, p.A + go, ok);
    }
#pragma unroll
    for (int i = 0; i < 2; i++) {            // B: 128 rows x 4 chunks = 512
        int id = tid + i * 256;
        int r = id >> 2, ch = id & 3;
        int gr = bn0 + r;
        bool ok = (gr < p.Nd);
        size_t go = (size_t)gr * p.ldb + k0 + ch * 8;
        cpa16(base + 10240 + r * 80 + ch * 16, p.Bm + go, ok);
    }
    CPA_COMMIT();
}

__device__ void gemm_core(const GP& p, char* smem, int bm0, int bn0) {
    const uint32_t sb = (uint32_t)__cvta_generic_to_shared(smem);
    const int tid  = threadIdx.x;
    const int lane = tid & 31;
    const int warp = tid >> 5;
    const int wm0 = (warp >> 2) * 64;   // 0,64
    const int wn0 = (warp & 3) * 32;    // 0,32,64,96

    float acc[4][4][4];
#pragma unroll
    for (int i = 0; i < 4; i++)
#pragma unroll
        for (int j = 0; j < 4; j++) {
            acc[i][j][0] = 0.f; acc[i][j][1] = 0.f; acc[i][j][2] = 0.f; acc[i][j][3] = 0.f;
        }

    const int nk = p.Kd >> 5;
    issue_loads(p, sb, 0, bm0, bn0, 0, tid);
    if (nk > 1) issue_loads(p, sb, 1, bm0, bn0, 32, tid);

    for (int it = 0; it < nk; it++) {
        if (it + 1 < nk) CPA_WAIT1(); else CPA_WAIT0();
        __syncthreads();

        const uint32_t base = sb + (it & 1) * STG;
#pragma unroll
        for (int kk = 0; kk < 32; kk += 16) {
            // B fragments for full warp n-extent 32
            uint32_t bA0, bA1, bA2, bA3, bB0, bB1, bB2, bB3;
            {
                uint32_t bo = base + 10240u
                    + (uint32_t)((wn0 + (lane & 15)) * 80 + (kk + ((lane >> 4) << 3)) * 2);
                ldsm4(bA0, bA1, bA2, bA3, bo);
                ldsm4(bB0, bB1, bB2, bB3, bo + 16 * 80u);
            }
            // A fragments double-buffered across mt
            uint32_t Af[2][4];
            const uint32_t ao0 = base
                + (uint32_t)((wm0 + (lane & 15)) * 80 + (kk + ((lane >> 4) << 3)) * 2);
            ldsm4(Af[0][0], Af[0][1], Af[0][2], Af[0][3], ao0);
#pragma unroll
            for (int mt = 0; mt < 4; mt++) {
                const int cur = mt & 1, nxt = cur ^ 1;
                if (mt < 3) {
                    uint32_t ao = ao0 + (uint32_t)((mt + 1) * 16 * 80);
                    ldsm4(Af[nxt][0], Af[nxt][1], Af[nxt][2], Af[nxt][3], ao);
                }
                mma16816h(acc[mt][0][0], acc[mt][0][1], acc[mt][0][2], acc[mt][0][3],
                          Af[cur][0], Af[cur][1], Af[cur][2], Af[cur][3], bA0, bA2);
                mma16816h(acc[mt][1][0], acc[mt][1][1], acc[mt][1][2], acc[mt][1][3],
                          Af[cur][0], Af[cur][1], Af[cur][2], Af[cur][3], bA1, bA3);
                mma16816h(acc[mt][2][0], acc[mt][2][1], acc[mt][2][2], acc[mt][2][3],
                          Af[cur][0], Af[cur][1], Af[cur][2], Af[cur][3], bB0, bB2);
                mma16816h(acc[mt][3][0], acc[mt][3][1], acc[mt][3][2], acc[mt][3][3],
                          Af[cur][0], Af[cur][1], Af[cur][2], Af[cur][3], bB1, bB3);
            }
        }
        __syncthreads();
        if (it + 2 < nk) issue_loads(p, sb, it & 1, bm0, bn0, (it + 2) << 5, tid);
    }

    // epilogue
#pragma unroll
    for (int mt = 0; mt < 4; mt++)
#pragma unroll
        for (int nt = 0; nt < 4; nt++) {
            int r0 = bm0 + wm0 + mt * 16 + (lane >> 2);
            int cc = bn0 + wn0 + nt * 8 + ((lane & 3) << 1);
            if (cc < p.Nd) {
                float b0 = p.bias ? p.bias[cc]     : 0.f;
                float b1 = p.bias ? p.bias[cc + 1] : 0.f;
                if (r0 < p.Md) {
                    float x0 = acc[mt][nt][0] + b0, x1 = acc[mt][nt][1] + b1;
                    *(float2*)&p.C[(size_t)r0 * p.ldc + cc] = make_float2(x0, x1);
                    if (p.Ch) cvt2h(&p.Ch[(size_t)r0 * p.ldc + cc], x0, x1);
                }
                if (r0 + 8 < p.Md) {
                    float x2 = acc[mt][nt][2] + b0, x3 = acc[mt][nt][3] + b1;
                    *(float2*)&p.C[(size_t)(r0 + 8) * p.ldc + cc] = make_float2(x2, x3);
                    if (p.Ch) cvt2h(&p.Ch[(size_t)(r0 + 8) * p.ldc + cc], x2, x3);
                }
            }
        }
}

// front: by<16 -> xl part (k/v), by>=16 -> sfT part (Ek/Ev); z selects pair
__global__ __launch_bounds__(256, 2) void front_gemm(GP xk, GP xv, GP sk, GP sv) {
    extern __shared__ char dsm[];
    int by = blockIdx.y;
    GP p;
    int bm0;
    if (by < 16) { p = blockIdx.z ? xv : xk; bm0 = by * 128; }
    else         { p = blockIdx.z ? sv : sk; bm0 = (by - 16) * 128; }
    gemm_core(p, dsm, bm0, blockIdx.x * 128);
}
__global__ __launch_bounds__(256, 2) void one_gemm(GP p) {
    extern __shared__ char dsm[];
    gemm_core(p, dsm, blockIdx.y * 128, blockIdx.x * 128);
}

// ---------------- normalize Ek rows -> Ekn (fp16); q[j] ----------------
__global__ void prep_rows(const float* __restrict__ Ww) {
    int j = blockIdx.x;
    const float* ek = g_Ek + (size_t)j * CH;
    const float* ev = g_Ev + (size_t)j * CH;
    float ss = 0.f, dq = 0.f;
    for (int o = threadIdx.x; o < CH; o += 256) {
        float e = ek[o];
        ss += e * e;
        dq += ev[o] * Ww[o];
    }
#pragma unroll
    for (int off = 16; off; off >>= 1) {
        ss += __shfl_xor_sync(0xffffffffu, ss, off);
        dq += __shfl_xor_sync(0xffffffffu, dq, off);
    }
    __shared__ float s1[8], s2[8];
    int lane = threadIdx.x & 31, w = threadIdx.x >> 5;
    if (lane == 0) { s1[w] = ss; s2[w] = dq; }
    __syncthreads();
    if (threadIdx.x == 0) {
        float a = 0.f, q = 0.f;
        for (int i = 0; i < 8; i++) { a += s1[i]; q += s2[i]; }
        s1[0] = 1.f / fmaxf(sqrtf(a), EPSv);
        g_q[j] = q;
    }
    __syncthreads();
    float inv = s1[0];
    for (int o = threadIdx.x; o < CH; o += 256) {
        size_t idx = (size_t)j * CH + o;
        s_Ekn[idx] = __float2half_rn(ek[o] * inv);
    }
}

// ---------------- 1/||k[b]|| ----------------
__global__ void knorm_kernel() {
    int b = blockIdx.x;
    const float* kr = g_k + (size_t)b * CH;
    float ss = 0.f;
    for (int o = threadIdx.x; o < CH; o += 256) { float t = kr[o]; ss += t * t; }
#pragma unroll
    for (int off = 16; off; off >>= 1) ss += __shfl_xor_sync(0xffffffffu, ss, off);
    __shared__ float s1[8];
    int lane = threadIdx.x & 31, w = threadIdx.x >> 5;
    if (lane == 0) s1[w] = ss;
    __syncthreads();
    if (threadIdx.x == 0) {
        float a = 0.f;
        for (int i = 0; i < 8; i++) a += s1[i];
        g_ikn[b] = 1.f / fmaxf(sqrtf(a), EPSv);
    }
}

// ---------------- attention ----------------
__global__ void attn_kernel(const float* __restrict__ bw) {
    int b = blockIdx.x;
    int m = threadIdx.x;
    int n = threadIdx.y;
    int j = n * Mn + m;
    float inv = g_ikn[b];
    float c = g_att[(size_t)b * Jn + j] * inv;

    float mx = c;
#pragma unroll
    for (int off = 16; off; off >>= 1) mx = fmaxf(mx, __shfl_xor_sync(0xffffffffu, mx, off));
    float e = __expf(c - mx);
    float s = e;
#pragma unroll
    for (int off = 16; off; off >>= 1) s += __shfl_xor_sync(0xffffffffu, s, off);
    float w = e / s;

    float lq = w * g_q[j];
#pragma unroll
    for (int off = 16; off; off >>= 1) lq += __shfl_xor_sync(0xffffffffu, lq, off);

    __shared__ float sl[NCLS];
    if (m == 0) sl[n] = lq + bw[0];
    __syncthreads();

    float fmx = -1e30f;
#pragma unroll
    for (int i = 0; i < NCLS; i++) fmx = fmaxf(fmx, sl[i]);
    float fs = 0.f;
#pragma unroll
    for (int i = 0; i < NCLS; i++) fs += __expf(sl[i] - fmx);
    float fw = __expf(sl[n] - fmx) / fs;

    s_att[(size_t)b * Jn + j] = __float2half_rn(fw * w);
}

// ---------------- output projection (8 rows/block) ----------------
__global__ void out_kernel(const float* __restrict__ Wout, const float* __restrict__ bout,
                           float* __restrict__ out) {
    __shared__ float sh[8][NCLS];
    int lane = threadIdx.x & 31, w = threadIdx.x >> 5;
    for (int bb = 0; bb < 8; bb++) {
        int b = blockIdx.x * 8 + bb;
        const float* vr = g_v  + (size_t)b * CH;
        const float* fr = g_fE + (size_t)b * CH;
        float acc[NCLS];
#pragma unroll
        for (int c = 0; c < NCLS; c++) acc[c] = 0.f;
        for (int o = threadIdx.x; o < CH; o += 256) {
            float rv = fmaxf(vr[o], 0.f);
            float rf = fmaxf(fr[o], 0.f);
#pragma unroll
            for (int c = 0; c < NCLS; c++)
                acc[c] += rv * Wout[(size_t)c * (2 * CH) + o] + rf * Wout[(size_t)c * (2 * CH) + CH + o];
        }
#pragma unroll
        for (int c = 0; c < NCLS; c++) {
            float vsum = acc[c];
#pragma unroll
            for (int off = 16; off; off >>= 1) vsum += __shfl_xor_sync(0xffffffffu, vsum, off);
            if (lane == 0) sh[w][c] = vsum;
        }
        __syncthreads();
        if (threadIdx.x < NCLS) {
            float s = 0.f;
            for (int wi = 0; wi < 8; wi++) s += sh[wi][threadIdx.x];
            out[(size_t)b * NCLS + threadIdx.x] = s + bout[threadIdx.x];
        }
        __syncthreads();
    }
}

// ---------------- host launcher ----------------
extern "C" void kernel_launch(void* const* d_in, const int* in_sizes, int n_in,
                              void* d_out, int out_size) {
    const float* x    = (const float*)d_in[0];
    const float* sf   = (const float*)d_in[1];
    const float* Wk   = (const float*)d_in[2];
    const float* bk   = (const float*)d_in[3];
    const float* Wv   = (const float*)d_in[4];
    const float* bv   = (const float*)d_in[5];
    const float* WEk  = (const float*)d_in[6];
    const float* bEk  = (const float*)d_in[7];
    const float* WEv  = (const float*)d_in[8];
    const float* bEv  = (const float*)d_in[9];
    const float* Ww   = (const float*)d_in[10];
    const float* bw   = (const float*)d_in[11];
    const float* Wout = (const float*)d_in[12];
    const float* bout = (const float*)d_in[13];
    float* out = (float*)d_out;

    h16 *xl, *sfT, *pWk, *pWv, *pWEk, *pWEv, *pk16, *Ekn, *att16, *EvT;
    float *p_Ek, *p_Ev, *p_k, *p_v, *p_att, *p_fE;
    cudaGetSymbolAddress((void**)&xl,   s_xl);
    cudaGetSymbolAddress((void**)&sfT,  s_sfT);
    cudaGetSymbolAddress((void**)&pWk,  s_Wk);
    cudaGetSymbolAddress((void**)&pWv,  s_Wv);
    cudaGetSymbolAddress((void**)&pWEk, s_WEk);
    cudaGetSymbolAddress((void**)&pWEv, s_WEv);
    cudaGetSymbolAddress((void**)&pk16, s_k);
    cudaGetSymbolAddress((void**)&Ekn,  s_Ekn);
    cudaGetSymbolAddress((void**)&att16, s_att);
    cudaGetSymbolAddress((void**)&EvT,  s_EvT);
    cudaGetSymbolAddress((void**)&p_Ek,  g_Ek);
    cudaGetSymbolAddress((void**)&p_Ev,  g_Ev);
    cudaGetSymbolAddress((void**)&p_k,   g_k);
    cudaGetSymbolAddress((void**)&p_v,   g_v);
    cudaGetSymbolAddress((void**)&p_att, g_att);
    cudaGetSymbolAddress((void**)&p_fE,  g_fE);

    static bool attr_done = false;
    if (!attr_done) {
        cudaFuncSetAttribute(front_gemm, cudaFuncAttributeMaxDynamicSharedMemorySize, GEMM_SMEM);
        cudaFuncSetAttribute(one_gemm,   cudaFuncAttributeMaxDynamicSharedMemorySize, GEMM_SMEM);
        attr_done = true;
    }

    // 1) converters
    transpose_sf<<<dim3(CIN / 32, NCLS), dim3(32, 32)>>>(sf);
    {
        CvtJob j0 = {Wk,  pWk};
        CvtJob j1 = {Wv,  pWv};
        CvtJob j2 = {WEk, pWEk};
        CvtJob j3 = {WEv, pWEv};
        convert4<<<dim3((CH * CIN / 4 + 255) / 256, 1, 4), 256>>>(j0, j1, j2, j3, CH * CIN / 4);
    }
    cvt_xl<<<Bn, 256>>>(x);

    // 2) fused front GEMMs: 352 CTAs (1.19 waves at 2 CTA/SM)
    {
        GP xk = {xl,  CIN, pWk,  CIN, bk,  p_k,  pk16,    CH, Bn, CH, CIN};
        GP xv = {xl,  CIN, pWv,  CIN, bv,  p_v,  nullptr, CH, Bn, CH, CIN};
        GP sk = {sfT, CIN, pWEk, CIN, bEk, p_Ek, nullptr, CH, Jn, CH, CIN};
        GP sv = {sfT, CIN, pWEv, CIN, bEv, p_Ev, nullptr, CH, Jn, CH, CIN};
        front_gemm<<<dim3(CH / 128, 22, 2), 256, GEMM_SMEM>>>(xk, xv, sk, sv);
    }

    // 3) prep
    prep_rows<<<Jn, 256>>>(Ww);
    evt_cvt<<<dim3(Jn / 32, CH / 32), dim3(32, 32)>>>();
    knorm_kernel<<<Bn, 256>>>();

    // 4) cos = k @ Ekn^T  (96 CTAs)
    {
        GP p = {pk16, CH, Ekn, CH, nullptr, p_att, nullptr, Jn, Bn, Jn, CH};
        one_gemm<<<dim3((Jn + 127) / 128, Bn / 128, 1), 256, GEMM_SMEM>>>(p);
    }

    // 5) softmaxes
    attn_kernel<<<Bn, dim3(32, NCLS)>>>(bw);

    // 6) fE = g @ EvT^T  (128 CTAs)
    {
        GP p = {att16, Jn, EvT, Jn, nullptr, p_fE, nullptr, CH, Bn, CH, Jn};
        one_gemm<<<dim3(CH / 128, Bn / 128, 1), 256, GEMM_SMEM>>>(p);
    }

    // 7) output projection
    out_kernel<<<Bn / 8, 256>>>(Wout, bout, out);
}

// round 16
// speedup vs baseline: 2.8273x; 1.0905x over previous
#include <cuda_runtime.h>
#include <cuda_fp16.h>
#include <cstdint>
#include <math.h>

#define Bn    2048
#define Tn    8
#define CIN   2048
#define CH    1024
#define Mn    32
#define NCLS  21
#define Jn    672
#define EPSv  1e-8f

typedef __half h16;

// ---------------- scratch (device globals) ----------------
__device__ __align__(128) h16 s_xl [Bn * CIN];
__device__ __align__(128) h16 s_sfT[Jn * CIN];
__device__ __align__(128) h16 s_Wk [CH * CIN];
__device__ __align__(128) h16 s_Wv [CH * CIN];
__device__ __align__(128) h16 s_WEk[CH * CIN];
__device__ __align__(128) h16 s_WEv[CH * CIN];
__device__ __align__(128) h16 s_k  [Bn * CH];
__device__ __align__(128) h16 s_Ekn[Jn * CH];
__device__ __align__(128) h16 s_att[Bn * Jn];
__device__ __align__(128) h16 s_EvT[CH * Jn];
__device__ float g_Ek [Jn * CH];
__device__ float g_Ev [Jn * CH];
__device__ float g_q  [Jn];
__device__ float g_k  [Bn * CH];
__device__ float g_v  [Bn * CH];
__device__ float g_ikn[Bn];
__device__ float g_att[Bn * Jn];
__device__ float g_fE [Bn * CH];

// ---------------- convert helpers ----------------
__device__ __forceinline__ void cvt2h(h16* d, float x, float y) {
    *(__half2*)d = __floats2half2_rn(x, y);
}

// ---------------- converters ----------------
__global__ void transpose_sf(const float* __restrict__ sf) {
    __shared__ float tile[32][33];
    int n  = blockIdx.y;
    int c0 = blockIdx.x * 32;
    tile[threadIdx.y][threadIdx.x] = sf[((size_t)n * CIN + (c0 + threadIdx.y)) * Mn + threadIdx.x];
    __syncthreads();
    size_t o = ((size_t)(n * Mn + threadIdx.y)) * CIN + c0 + threadIdx.x;
    s_sfT[o] = __float2half_rn(tile[threadIdx.x][threadIdx.y]);
}

struct CvtJob { const float* src; h16* dst; };
__global__ void convert4(CvtJob j0, CvtJob j1, CvtJob j2, CvtJob j3, int n4) {
    CvtJob j = (blockIdx.z == 0) ? j0 : (blockIdx.z == 1) ? j1 : (blockIdx.z == 2) ? j2 : j3;
    int i = blockIdx.x * blockDim.x + threadIdx.x;
    if (i < n4) {
        float4 v = ((const float4*)j.src)[i];
        cvt2h(j.dst + i * 4,     v.x, v.y);
        cvt2h(j.dst + i * 4 + 2, v.z, v.w);
    }
}

__global__ void cvt_xl(const float* __restrict__ x) {
    int r = blockIdx.x;
    const float4* src = (const float4*)(x + (size_t)r * Tn * CIN + (size_t)(Tn - 1) * CIN);
#pragma unroll
    for (int i = 0; i < 2; i++) {
        int c4 = threadIdx.x + i * 256;
        float4 v = src[c4];
        size_t o = (size_t)r * CIN + c4 * 4;
        cvt2h(&s_xl[o],     v.x, v.y);
        cvt2h(&s_xl[o + 2], v.z, v.w);
    }
}

__global__ void evt_cvt() {
    __shared__ float tile[32][33];
    int j0 = blockIdx.x * 32;
    int c0 = blockIdx.y * 32;
    tile[threadIdx.y][threadIdx.x] = g_Ev[(size_t)(j0 + threadIdx.y) * CH + c0 + threadIdx.x];
    __syncthreads();
    size_t o = (size_t)(c0 + threadIdx.y) * Jn + j0 + threadIdx.x;
    s_EvT[o] = __float2half_rn(tile[threadIdx.x][threadIdx.y]);
}

// ---------------- PTX helpers ----------------
__device__ __forceinline__ void ldsm4(uint32_t &r0, uint32_t &r1, uint32_t &r2, uint32_t &r3,
                                      uint32_t addr) {
    asm volatile("ldmatrix.sync.aligned.m8n8.x4.shared.b16 {%0,%1,%2,%3}, [%4];"
                 : "=r"(r0), "=r"(r1), "=r"(r2), "=r"(r3) : "r"(addr));
}
__device__ __forceinline__ void mma16816h(float &c0, float &c1, float &c2, float &c3,
                                          uint32_t a0, uint32_t a1, uint32_t a2, uint32_t a3,
                                          uint32_t b0, uint32_t b1) {
    asm volatile("mma.sync.aligned.m16n8k16.row.col.f32.f16.f16.f32 "
                 "{%0,%1,%2,%3}, {%4,%5,%6,%7}, {%8,%9}, {%0,%1,%2,%3};"
                 : "+f"(c0), "+f"(c1), "+f"(c2), "+f"(c3)
                 : "r"(a0), "r"(a1), "r"(a2), "r"(a3), "r"(b0), "r"(b1));
}
__device__ __forceinline__ void cpa16(uint32_t dst, const void* src, bool pred) {
    int sz = pred ? 16 : 0;
    asm volatile("cp.async.cg.shared.global [%0], [%1], 16, %2;"
                 :: "r"(dst), "l"(src), "r"(sz));
}
#define CPA_COMMIT() asm volatile("cp.async.commit_group;" ::: "memory")
#define CPA_WAIT1()  asm volatile("cp.async.wait_group 1;" ::: "memory")
#define CPA_WAIT0()  asm volatile("cp.async.wait_group 0;" ::: "memory")

// =====================================================================
// fp16 TN GEMM: C = A @ B^T + bias   (A: Md x Kd, B: Nd x Kd, fp16)
// CTA tile 128x128, 256 threads, 8 warps (2x4), warp tile 64x32.
// KT=64 (144B padded rows, conflict-free), 2-stage cp.async, 2 CTAs/SM.
// K tail handled by zero-fill predicates (zeros are mma-neutral).
// =====================================================================
struct GP {
    const h16 *A; int lda;
    const h16 *Bm; int ldb;
    const float* bias;
    float* C; h16 *Ch; int ldc;
    int Md, Nd, Kd;
};

#define KT    64
#define ROWB  144
#define HALF_STG (128 * ROWB)          // 18432 B: A block
#define STG   (2 * HALF_STG)           // 36864 B per stage
#define GEMM_SMEM (2 * STG)            // 73728 B

__device__ __forceinline__ void issue_loads(const GP& p, uint32_t sb, int stage,
                                            int bm0, int bn0, int k0, int tid) {
    uint32_t base = sb + stage * STG;
#pragma unroll
    for (int i = 0; i < 4; i++) {            // A: 128 rows x 8 chunks = 1024
        int id = tid + i * 256;
        int r = id >> 3, ch = id & 7;
        int gr = bm0 + r;
        bool ok = (gr < p.Md) && (k0 + ch * 8 < p.Kd);
        cpa16(base + r * ROWB + ch * 16, p.A + (size_t)gr * p.lda + k0 + ch * 8, ok);
    }
#pragma unroll
    for (int i = 0; i < 4; i++) {            // B: 128 rows x 8 chunks = 1024
        int id = tid + i * 256;
        int r = id >> 3, ch = id & 7;
        int gr = bn0 + r;
        bool ok = (gr < p.Nd) && (k0 + ch * 8 < p.Kd);
        cpa16(base + HALF_STG + r * ROWB + ch * 16, p.Bm + (size_t)gr * p.ldb + k0 + ch * 8, ok);
    }
    CPA_COMMIT();
}

__device__ void gemm_core(const GP& p, char* smem, int bm0, int bn0) {
    const uint32_t sb = (uint32_t)__cvta_generic_to_shared(smem);
    const int tid  = threadIdx.x;
    const int lane = tid & 31;
    const int warp = tid >> 5;
    const int wm0 = (warp >> 2) * 64;   // 0,64
    const int wn0 = (warp & 3) * 32;    // 0,32,64,96

    float acc[4][4][4];
#pragma unroll
    for (int i = 0; i < 4; i++)
#pragma unroll
        for (int j = 0; j < 4; j++) {
            acc[i][j][0] = 0.f; acc[i][j][1] = 0.f; acc[i][j][2] = 0.f; acc[i][j][3] = 0.f;
        }

    const int nk = (p.Kd + KT - 1) >> 6;
    issue_loads(p, sb, 0, bm0, bn0, 0, tid);
    if (nk > 1) issue_loads(p, sb, 1, bm0, bn0, KT, tid);

    for (int it = 0; it < nk; it++) {
        if (it + 1 < nk) CPA_WAIT1(); else CPA_WAIT0();
        __syncthreads();

        const uint32_t base = sb + (it & 1) * STG;
#pragma unroll
        for (int kk = 0; kk < KT; kk += 16) {
            // B fragments for full warp n-extent 32
            uint32_t bA0, bA1, bA2, bA3, bB0, bB1, bB2, bB3;
            {
                uint32_t bo = base + (uint32_t)HALF_STG
                    + (uint32_t)((wn0 + (lane & 15)) * ROWB + (kk + ((lane >> 4) << 3)) * 2);
                ldsm4(bA0, bA1, bA2, bA3, bo);
                ldsm4(bB0, bB1, bB2, bB3, bo + 16 * ROWB);
            }
            // A fragments double-buffered across mt
            uint32_t Af[2][4];
            const uint32_t ao0 = base
                + (uint32_t)((wm0 + (lane & 15)) * ROWB + (kk + ((lane >> 4) << 3)) * 2);
            ldsm4(Af[0][0], Af[0][1], Af[0][2], Af[0][3], ao0);
#pragma unroll
            for (int mt = 0; mt < 4; mt++) {
                const int cur = mt & 1, nxt = cur ^ 1;
                if (mt < 3) {
                    uint32_t ao = ao0 + (uint32_t)((mt + 1) * 16 * ROWB);
                    ldsm4(Af[nxt][0], Af[nxt][1], Af[nxt][2], Af[nxt][3], ao);
                }
                mma16816h(acc[mt][0][0], acc[mt][0][1], acc[mt][0][2], acc[mt][0][3],
                          Af[cur][0], Af[cur][1], Af[cur][2], Af[cur][3], bA0, bA2);
                mma16816h(acc[mt][1][0], acc[mt][1][1], acc[mt][1][2], acc[mt][1][3],
                          Af[cur][0], Af[cur][1], Af[cur][2], Af[cur][3], bA1, bA3);
                mma16816h(acc[mt][2][0], acc[mt][2][1], acc[mt][2][2], acc[mt][2][3],
                          Af[cur][0], Af[cur][1], Af[cur][2], Af[cur][3], bB0, bB2);
                mma16816h(acc[mt][3][0], acc[mt][3][1], acc[mt][3][2], acc[mt][3][3],
                          Af[cur][0], Af[cur][1], Af[cur][2], Af[cur][3], bB1, bB3);
            }
        }
        __syncthreads();
        if (it + 2 < nk) issue_loads(p, sb, it & 1, bm0, bn0, (it + 2) << 6, tid);
    }

    // epilogue
#pragma unroll
    for (int mt = 0; mt < 4; mt++)
#pragma unroll
        for (int nt = 0; nt < 4; nt++) {
            int r0 = bm0 + wm0 + mt * 16 + (lane >> 2);
            int cc = bn0 + wn0 + nt * 8 + ((lane & 3) << 1);
            if (cc < p.Nd) {
                float b0 = p.bias ? p.bias[cc]     : 0.f;
                float b1 = p.bias ? p.bias[cc + 1] : 0.f;
                if (r0 < p.Md) {
                    float x0 = acc[mt][nt][0] + b0, x1 = acc[mt][nt][1] + b1;
                    *(float2*)&p.C[(size_t)r0 * p.ldc + cc] = make_float2(x0, x1);
                    if (p.Ch) cvt2h(&p.Ch[(size_t)r0 * p.ldc + cc], x0, x1);
                }
                if (r0 + 8 < p.Md) {
                    float x2 = acc[mt][nt][2] + b0, x3 = acc[mt][nt][3] + b1;
                    *(float2*)&p.C[(size_t)(r0 + 8) * p.ldc + cc] = make_float2(x2, x3);
                    if (p.Ch) cvt2h(&p.Ch[(size_t)(r0 + 8) * p.ldc + cc], x2, x3);
                }
            }
        }
}

// front: by<16 -> xl part (k/v), by>=16 -> sfT part (Ek/Ev); z selects pair
__global__ __launch_bounds__(256, 2) void front_gemm(GP xk, GP xv, GP sk, GP sv) {
    extern __shared__ char dsm[];
    int by = blockIdx.y;
    GP p;
    int bm0;
    if (by < 16) { p = blockIdx.z ? xv : xk; bm0 = by * 128; }
    else         { p = blockIdx.z ? sv : sk; bm0 = (by - 16) * 128; }
    gemm_core(p, dsm, bm0, blockIdx.x * 128);
}
__global__ __launch_bounds__(256, 2) void one_gemm(GP p) {
    extern __shared__ char dsm[];
    gemm_core(p, dsm, blockIdx.y * 128, blockIdx.x * 128);
}

// ---------------- merged: prep_rows (blocks 0..Jn-1) + knorm (blocks Jn..Jn+Bn-1) ----------------
__global__ void prep_rows_knorm(const float* __restrict__ Ww) {
    int blk = blockIdx.x;
    int lane = threadIdx.x & 31, w = threadIdx.x >> 5;
    if (blk < Jn) {
        int j = blk;
        const float* ek = g_Ek + (size_t)j * CH;
        const float* ev = g_Ev + (size_t)j * CH;
        float ss = 0.f, dq = 0.f;
        for (int o = threadIdx.x; o < CH; o += 256) {
            float e = ek[o];
            ss += e * e;
            dq += ev[o] * Ww[o];
        }
#pragma unroll
        for (int off = 16; off; off >>= 1) {
            ss += __shfl_xor_sync(0xffffffffu, ss, off);
            dq += __shfl_xor_sync(0xffffffffu, dq, off);
        }
        __shared__ float s1[8], s2[8];
        if (lane == 0) { s1[w] = ss; s2[w] = dq; }
        __syncthreads();
        if (threadIdx.x == 0) {
            float a = 0.f, q = 0.f;
            for (int i = 0; i < 8; i++) { a += s1[i]; q += s2[i]; }
            s1[0] = 1.f / fmaxf(sqrtf(a), EPSv);
            g_q[j] = q;
        }
        __syncthreads();
        float inv = s1[0];
        for (int o = threadIdx.x; o < CH; o += 256) {
            size_t idx = (size_t)j * CH + o;
            s_Ekn[idx] = __float2half_rn(ek[o] * inv);
        }
    } else {
        int b = blk - Jn;
        const float* kr = g_k + (size_t)b * CH;
        float ss = 0.f;
        for (int o = threadIdx.x; o < CH; o += 256) { float t = kr[o]; ss += t * t; }
#pragma unroll
        for (int off = 16; off; off >>= 1) ss += __shfl_xor_sync(0xffffffffu, ss, off);
        __shared__ float s1[8];
        if (lane == 0) s1[w] = ss;
        __syncthreads();
        if (threadIdx.x == 0) {
            float a = 0.f;
            for (int i = 0; i < 8; i++) a += s1[i];
            g_ikn[b] = 1.f / fmaxf(sqrtf(a), EPSv);
        }
    }
}

// ---------------- attention ----------------
__global__ void attn_kernel(const float* __restrict__ bw) {
    int b = blockIdx.x;
    int m = threadIdx.x;
    int n = threadIdx.y;
    int j = n * Mn + m;
    float inv = g_ikn[b];
    float c = g_att[(size_t)b * Jn + j] * inv;

    float mx = c;
#pragma unroll
    for (int off = 16; off; off >>= 1) mx = fmaxf(mx, __shfl_xor_sync(0xffffffffu, mx, off));
    float e = __expf(c - mx);
    float s = e;
#pragma unroll
    for (int off = 16; off; off >>= 1) s += __shfl_xor_sync(0xffffffffu, s, off);
    float w = e / s;

    float lq = w * g_q[j];
#pragma unroll
    for (int off = 16; off; off >>= 1) lq += __shfl_xor_sync(0xffffffffu, lq, off);

    __shared__ float sl[NCLS];
    if (m == 0) sl[n] = lq + bw[0];
    __syncthreads();

    float fmx = -1e30f;
#pragma unroll
    for (int i = 0; i < NCLS; i++) fmx = fmaxf(fmx, sl[i]);
    float fs = 0.f;
#pragma unroll
    for (int i = 0; i < NCLS; i++) fs += __expf(sl[i] - fmx);
    float fw = __expf(sl[n] - fmx) / fs;

    s_att[(size_t)b * Jn + j] = __float2half_rn(fw * w);
}

// ---------------- output projection (8 rows/block) ----------------
__global__ void out_kernel(const float* __restrict__ Wout, const float* __restrict__ bout,
                           float* __restrict__ out) {
    __shared__ float sh[8][NCLS];
    int lane = threadIdx.x & 31, w = threadIdx.x >> 5;
    for (int bb = 0; bb < 8; bb++) {
        int b = blockIdx.x * 8 + bb;
        const float* vr = g_v  + (size_t)b * CH;
        const float* fr = g_fE + (size_t)b * CH;
        float acc[NCLS];
#pragma unroll
        for (int c = 0; c < NCLS; c++) acc[c] = 0.f;
        for (int o = threadIdx.x; o < CH; o += 256) {
            float rv = fmaxf(vr[o], 0.f);
            float rf = fmaxf(fr[o], 0.f);
#pragma unroll
            for (int c = 0; c < NCLS; c++)
                acc[c] += rv * Wout[(size_t)c * (2 * CH) + o] + rf * Wout[(size_t)c * (2 * CH) + CH + o];
        }
#pragma unroll
        for (int c = 0; c < NCLS; c++) {
            float vsum = acc[c];
#pragma unroll
            for (int off = 16; off; off >>= 1) vsum += __shfl_xor_sync(0xffffffffu, vsum, off);
            if (lane == 0) sh[w][c] = vsum;
        }
        __syncthreads();
        if (threadIdx.x < NCLS) {
            float s = 0.f;
            for (int wi = 0; wi < 8; wi++) s += sh[wi][threadIdx.x];
            out[(size_t)b * NCLS + threadIdx.x] = s + bout[threadIdx.x];
        }
        __syncthreads();
    }
}

// ---------------- host launcher ----------------
extern "C" void kernel_launch(void* const* d_in, const int* in_sizes, int n_in,
                              void* d_out, int out_size) {
    const float* x    = (const float*)d_in[0];
    const float* sf   = (const float*)d_in[1];
    const float* Wk   = (const float*)d_in[2];
    const float* bk   = (const float*)d_in[3];
    const float* Wv   = (const float*)d_in[4];
    const float* bv   = (const float*)d_in[5];
    const float* WEk  = (const float*)d_in[6];
    const float* bEk  = (const float*)d_in[7];
    const float* WEv  = (const float*)d_in[8];
    const float* bEv  = (const float*)d_in[9];
    const float* Ww   = (const float*)d_in[10];
    const float* bw   = (const float*)d_in[11];
    const float* Wout = (const float*)d_in[12];
    const float* bout = (const float*)d_in[13];
    float* out = (float*)d_out;

    h16 *xl, *sfT, *pWk, *pWv, *pWEk, *pWEv, *pk16, *Ekn, *att16, *EvT;
    float *p_Ek, *p_Ev, *p_k, *p_v, *p_att, *p_fE;
    cudaGetSymbolAddress((void**)&xl,   s_xl);
    cudaGetSymbolAddress((void**)&sfT,  s_sfT);
    cudaGetSymbolAddress((void**)&pWk,  s_Wk);
    cudaGetSymbolAddress((void**)&pWv,  s_Wv);
    cudaGetSymbolAddress((void**)&pWEk, s_WEk);
    cudaGetSymbolAddress((void**)&pWEv, s_WEv);
    cudaGetSymbolAddress((void**)&pk16, s_k);
    cudaGetSymbolAddress((void**)&Ekn,  s_Ekn);
    cudaGetSymbolAddress((void**)&att16, s_att);
    cudaGetSymbolAddress((void**)&EvT,  s_EvT);
    cudaGetSymbolAddress((void**)&p_Ek,  g_Ek);
    cudaGetSymbolAddress((void**)&p_Ev,  g_Ev);
    cudaGetSymbolAddress((void**)&p_k,   g_k);
    cudaGetSymbolAddress((void**)&p_v,   g_v);
    cudaGetSymbolAddress((void**)&p_att, g_att);
    cudaGetSymbolAddress((void**)&p_fE,  g_fE);

    static bool attr_done = false;
    if (!attr_done) {
        cudaFuncSetAttribute(front_gemm, cudaFuncAttributeMaxDynamicSharedMemorySize, GEMM_SMEM);
        cudaFuncSetAttribute(one_gemm,   cudaFuncAttributeMaxDynamicSharedMemorySize, GEMM_SMEM);
        attr_done = true;
    }

    // 1) converters
    transpose_sf<<<dim3(CIN / 32, NCLS), dim3(32, 32)>>>(sf);
    {
        CvtJob j0 = {Wk,  pWk};
        CvtJob j1 = {Wv,  pWv};
        CvtJob j2 = {WEk, pWEk};
        CvtJob j3 = {WEv, pWEv};
        convert4<<<dim3((CH * CIN / 4 + 255) / 256, 1, 4), 256>>>(j0, j1, j2, j3, CH * CIN / 4);
    }
    cvt_xl<<<Bn, 256>>>(x);

    // 2) fused front GEMMs: 352 CTAs (1.19 waves at 2 CTA/SM)
    {
        GP xk = {xl,  CIN, pWk,  CIN, bk,  p_k,  pk16,    CH, Bn, CH, CIN};
        GP xv = {xl,  CIN, pWv,  CIN, bv,  p_v,  nullptr, CH, Bn, CH, CIN};
        GP sk = {sfT, CIN, pWEk, CIN, bEk, p_Ek, nullptr, CH, Jn, CH, CIN};
        GP sv = {sfT, CIN, pWEv, CIN, bEv, p_Ev, nullptr, CH, Jn, CH, CIN};
        front_gemm<<<dim3(CH / 128, 22, 2), 256, GEMM_SMEM>>>(xk, xv, sk, sv);
    }

    // 3) prep: Ekn + q + k norms (merged), EvT convert
    prep_rows_knorm<<<Jn + Bn, 256>>>(Ww);
    evt_cvt<<<dim3(Jn / 32, CH / 32), dim3(32, 32)>>>();

    // 4) cos = k @ Ekn^T  (96 CTAs)
    {
        GP p = {pk16, CH, Ekn, CH, nullptr, p_att, nullptr, Jn, Bn, Jn, CH};
        one_gemm<<<dim3((Jn + 127) / 128, Bn / 128, 1), 256, GEMM_SMEM>>>(p);
    }

    // 5) softmaxes
    attn_kernel<<<Bn, dim3(32, NCLS)>>>(bw);

    // 6) fE = g @ EvT^T  (128 CTAs)  K=672 tail zero-filled
    {
        GP p = {att16, Jn, EvT, Jn, nullptr, p_fE, nullptr, CH, Bn, CH, Jn};
        one_gemm<<<dim3(CH / 128, Bn / 128, 1), 256, GEMM_SMEM>>>(p);
    }

    // 7) output projection
    out_kernel<<<Bn / 8, 256>>>(Wout, bout, out);
}

// round 17
// speedup vs baseline: 2.8889x; 1.0218x over previous
#include <cuda_runtime.h>
#include <cuda_fp16.h>
#include <cstdint>
#include <math.h>

#define Bn    2048
#define Tn    8
#define CIN   2048
#define CH    1024
#define Mn    32
#define NCLS  21
#define Jn    672
#define EPSv  1e-8f

typedef __half h16;

// ---------------- scratch (device globals) ----------------
__device__ __align__(128) h16 s_xl [Bn * CIN];
__device__ __align__(128) h16 s_sfT[Jn * CIN];
__device__ __align__(128) h16 s_Wk [CH * CIN];
__device__ __align__(128) h16 s_Wv [CH * CIN];
__device__ __align__(128) h16 s_WEk[CH * CIN];
__device__ __align__(128) h16 s_WEv[CH * CIN];
__device__ __align__(128) h16 s_k  [Bn * CH];
__device__ __align__(128) h16 s_Ekn[Jn * CH];
__device__ __align__(128) h16 s_att[Bn * Jn];
__device__ __align__(128) h16 s_EvT[CH * Jn];
__device__ float g_Ek [Jn * CH];
__device__ float g_Ev [Jn * CH];
__device__ float g_q  [Jn];
__device__ float g_k  [Bn * CH];
__device__ float g_v  [Bn * CH];
__device__ float g_ikn[Bn];
__device__ float g_att[2 * Bn * Jn];   // two split-K partials
__device__ float g_fE [2 * Bn * CH];   // two split-K partials

// ---------------- convert helpers ----------------
__device__ __forceinline__ void cvt2h(h16* d, float x, float y) {
    *(__half2*)d = __floats2half2_rn(x, y);
}

// ---------------- converters ----------------
__global__ void transpose_sf(const float* __restrict__ sf) {
    __shared__ float tile[32][33];
    int n  = blockIdx.y;
    int c0 = blockIdx.x * 32;
    tile[threadIdx.y][threadIdx.x] = sf[((size_t)n * CIN + (c0 + threadIdx.y)) * Mn + threadIdx.x];
    __syncthreads();
    size_t o = ((size_t)(n * Mn + threadIdx.y)) * CIN + c0 + threadIdx.x;
    s_sfT[o] = __float2half_rn(tile[threadIdx.x][threadIdx.y]);
}

// merged: 4 weight converts (blocks 0..8191) + xl extract (blocks 8192..10239)
__global__ void convert_all(const float* __restrict__ Wk, const float* __restrict__ Wv,
                            const float* __restrict__ WEk, const float* __restrict__ WEv,
                            const float* __restrict__ x) {
    int blk = blockIdx.x;
    if (blk < 8192) {
        int w = blk >> 11;                       // weight id 0..3
        int i = ((blk & 2047) << 8) + threadIdx.x; // float4 index, exactly CH*CIN/4
        const float* src = (w == 0) ? Wk : (w == 1) ? Wv : (w == 2) ? WEk : WEv;
        h16* dst = (w == 0) ? s_Wk : (w == 1) ? s_Wv : (w == 2) ? s_WEk : s_WEv;
        float4 v = ((const float4*)src)[i];
        cvt2h(dst + i * 4,     v.x, v.y);
        cvt2h(dst + i * 4 + 2, v.z, v.w);
    } else {
        int r = blk - 8192;
        const float4* src = (const float4*)(x + (size_t)r * Tn * CIN + (size_t)(Tn - 1) * CIN);
#pragma unroll
        for (int i = 0; i < 2; i++) {
            int c4 = threadIdx.x + i * 256;
            float4 v = src[c4];
            size_t o = (size_t)r * CIN + c4 * 4;
            cvt2h(&s_xl[o],     v.x, v.y);
            cvt2h(&s_xl[o + 2], v.z, v.w);
        }
    }
}

// ---------------- PTX helpers ----------------
__device__ __forceinline__ void ldsm4(uint32_t &r0, uint32_t &r1, uint32_t &r2, uint32_t &r3,
                                      uint32_t addr) {
    asm volatile("ldmatrix.sync.aligned.m8n8.x4.shared.b16 {%0,%1,%2,%3}, [%4];"
                 : "=r"(r0), "=r"(r1), "=r"(r2), "=r"(r3) : "r"(addr));
}
__device__ __forceinline__ void mma16816h(float &c0, float &c1, float &c2, float &c3,
                                          uint32_t a0, uint32_t a1, uint32_t a2, uint32_t a3,
                                          uint32_t b0, uint32_t b1) {
    asm volatile("mma.sync.aligned.m16n8k16.row.col.f32.f16.f16.f32 "
                 "{%0,%1,%2,%3}, {%4,%5,%6,%7}, {%8,%9}, {%0,%1,%2,%3};"
                 : "+f"(c0), "+f"(c1), "+f"(c2), "+f"(c3)
                 : "r"(a0), "r"(a1), "r"(a2), "r"(a3), "r"(b0), "r"(b1));
}
__device__ __forceinline__ void cpa16(uint32_t dst, const void* src, bool pred) {
    int sz = pred ? 16 : 0;
    asm volatile("cp.async.cg.shared.global [%0], [%1], 16, %2;"
                 :: "r"(dst), "l"(src), "r"(sz));
}
#define CPA_COMMIT() asm volatile("cp.async.commit_group;" ::: "memory")
#define CPA_WAIT1()  asm volatile("cp.async.wait_group 1;" ::: "memory")
#define CPA_WAIT0()  asm volatile("cp.async.wait_group 0;" ::: "memory")

// =====================================================================
// fp16 TN GEMM: C = A @ B^T + bias   (A: Md x Kd, B: Nd x Kd, fp16)
// CTA tile 128x128, 256 threads, 8 warps (2x4), warp tile 64x32.
// KT=64 (144B padded rows), 2-stage cp.async, 2 CTAs/SM, zero-fill K tail.
// =====================================================================
struct GP {
    const h16 *A; int lda;
    const h16 *Bm; int ldb;
    const float* bias;
    float* C; h16 *Ch; int ldc;
    int Md, Nd, Kd;
};

#define KT    64
#define ROWB  144
#define HALF_STG (128 * ROWB)
#define STG   (2 * HALF_STG)
#define GEMM_SMEM (2 * STG)

__device__ __forceinline__ void issue_loads(const GP& p, uint32_t sb, int stage,
                                            int bm0, int bn0, int k0, int tid) {
    uint32_t base = sb + stage * STG;
#pragma unroll
    for (int i = 0; i < 4; i++) {
        int id = tid + i * 256;
        int r = id >> 3, ch = id & 7;
        int gr = bm0 + r;
        bool ok = (gr < p.Md) && (k0 + ch * 8 < p.Kd);
        cpa16(base + r * ROWB + ch * 16, p.A + (size_t)gr * p.lda + k0 + ch * 8, ok);
    }
#pragma unroll
    for (int i = 0; i < 4; i++) {
        int id = tid + i * 256;
        int r = id >> 3, ch = id & 7;
        int gr = bn0 + r;
        bool ok = (gr < p.Nd) && (k0 + ch * 8 < p.Kd);
        cpa16(base + HALF_STG + r * ROWB + ch * 16, p.Bm + (size_t)gr * p.ldb + k0 + ch * 8, ok);
    }
    CPA_COMMIT();
}

__device__ void gemm_core(const GP& p, char* smem, int bm0, int bn0) {
    const uint32_t sb = (uint32_t)__cvta_generic_to_shared(smem);
    const int tid  = threadIdx.x;
    const int lane = tid & 31;
    const int warp = tid >> 5;
    const int wm0 = (warp >> 2) * 64;
    const int wn0 = (warp & 3) * 32;

    float acc[4][4][4];
#pragma unroll
    for (int i = 0; i < 4; i++)
#pragma unroll
        for (int j = 0; j < 4; j++) {
            acc[i][j][0] = 0.f; acc[i][j][1] = 0.f; acc[i][j][2] = 0.f; acc[i][j][3] = 0.f;
        }

    const int nk = (p.Kd + KT - 1) >> 6;
    issue_loads(p, sb, 0, bm0, bn0, 0, tid);
    if (nk > 1) issue_loads(p, sb, 1, bm0, bn0, KT, tid);

    for (int it = 0; it < nk; it++) {
        if (it + 1 < nk) CPA_WAIT1(); else CPA_WAIT0();
        __syncthreads();

        const uint32_t base = sb + (it & 1) * STG;
#pragma unroll
        for (int kk = 0; kk < KT; kk += 16) {
            uint32_t bA0, bA1, bA2, bA3, bB0, bB1, bB2, bB3;
            {
                uint32_t bo = base + (uint32_t)HALF_STG
                    + (uint32_t)((wn0 + (lane & 15)) * ROWB + (kk + ((lane >> 4) << 3)) * 2);
                ldsm4(bA0, bA1, bA2, bA3, bo);
                ldsm4(bB0, bB1, bB2, bB3, bo + 16 * ROWB);
            }
            uint32_t Af[2][4];
            const uint32_t ao0 = base
                + (uint32_t)((wm0 + (lane & 15)) * ROWB + (kk + ((lane >> 4) << 3)) * 2);
            ldsm4(Af[0][0], Af[0][1], Af[0][2], Af[0][3], ao0);
#pragma unroll
            for (int mt = 0; mt < 4; mt++) {
                const int cur = mt & 1, nxt = cur ^ 1;
                if (mt < 3) {
                    uint32_t ao = ao0 + (uint32_t)((mt + 1) * 16 * ROWB);
                    ldsm4(Af[nxt][0], Af[nxt][1], Af[nxt][2], Af[nxt][3], ao);
                }
                mma16816h(acc[mt][0][0], acc[mt][0][1], acc[mt][0][2], acc[mt][0][3],
                          Af[cur][0], Af[cur][1], Af[cur][2], Af[cur][3], bA0, bA2);
                mma16816h(acc[mt][1][0], acc[mt][1][1], acc[mt][1][2], acc[mt][1][3],
                          Af[cur][0], Af[cur][1], Af[cur][2], Af[cur][3], bA1, bA3);
                mma16816h(acc[mt][2][0], acc[mt][2][1], acc[mt][2][2], acc[mt][2][3],
                          Af[cur][0], Af[cur][1], Af[cur][2], Af[cur][3], bB0, bB2);
                mma16816h(acc[mt][3][0], acc[mt][3][1], acc[mt][3][2], acc[mt][3][3],
                          Af[cur][0], Af[cur][1], Af[cur][2], Af[cur][3], bB1, bB3);
            }
        }
        __syncthreads();
        if (it + 2 < nk) issue_loads(p, sb, it & 1, bm0, bn0, (it + 2) << 6, tid);
    }

    // epilogue
#pragma unroll
    for (int mt = 0; mt < 4; mt++)
#pragma unroll
        for (int nt = 0; nt < 4; nt++) {
            int r0 = bm0 + wm0 + mt * 16 + (lane >> 2);
            int cc = bn0 + wn0 + nt * 8 + ((lane & 3) << 1);
            if (cc < p.Nd) {
                float b0 = p.bias ? p.bias[cc]     : 0.f;
                float b1 = p.bias ? p.bias[cc + 1] : 0.f;
                if (r0 < p.Md) {
                    float x0 = acc[mt][nt][0] + b0, x1 = acc[mt][nt][1] + b1;
                    *(float2*)&p.C[(size_t)r0 * p.ldc + cc] = make_float2(x0, x1);
                    if (p.Ch) cvt2h(&p.Ch[(size_t)r0 * p.ldc + cc], x0, x1);
                }
                if (r0 + 8 < p.Md) {
                    float x2 = acc[mt][nt][2] + b0, x3 = acc[mt][nt][3] + b1;
                    *(float2*)&p.C[(size_t)(r0 + 8) * p.ldc + cc] = make_float2(x2, x3);
                    if (p.Ch) cvt2h(&p.Ch[(size_t)(r0 + 8) * p.ldc + cc], x2, x3);
                }
            }
        }
}

// front: by<16 -> xl part (k/v), by>=16 -> sfT part (Ek/Ev); z selects pair
__global__ __launch_bounds__(256, 2) void front_gemm(GP xk, GP xv, GP sk, GP sv) {
    extern __shared__ char dsm[];
    int by = blockIdx.y;
    GP p;
    int bm0;
    if (by < 16) { p = blockIdx.z ? xv : xk; bm0 = by * 128; }
    else         { p = blockIdx.z ? sv : sk; bm0 = (by - 16) * 128; }
    gemm_core(p, dsm, bm0, blockIdx.x * 128);
}
// split-K wrapper: z selects K-half descriptor
__global__ __launch_bounds__(256, 2) void split_gemm(GP p0, GP p1) {
    extern __shared__ char dsm[];
    GP p = blockIdx.z ? p1 : p0;
    gemm_core(p, dsm, blockIdx.y * 128, blockIdx.x * 128);
}

// ---------------- merged prep: Ekn+q (0..Jn), knorm (Jn..Jn+Bn), EvT tiles (rest) ----------------
__global__ void prep_evt(const float* __restrict__ Ww) {
    int blk = blockIdx.x;
    int lane = threadIdx.x & 31, w = threadIdx.x >> 5;
    if (blk < Jn) {
        int j = blk;
        const float* ek = g_Ek + (size_t)j * CH;
        const float* ev = g_Ev + (size_t)j * CH;
        float ss = 0.f, dq = 0.f;
        for (int o = threadIdx.x; o < CH; o += 256) {
            float e = ek[o];
            ss += e * e;
            dq += ev[o] * Ww[o];
        }
#pragma unroll
        for (int off = 16; off; off >>= 1) {
            ss += __shfl_xor_sync(0xffffffffu, ss, off);
            dq += __shfl_xor_sync(0xffffffffu, dq, off);
        }
        __shared__ float s1[8], s2[8];
        if (lane == 0) { s1[w] = ss; s2[w] = dq; }
        __syncthreads();
        if (threadIdx.x == 0) {
            float a = 0.f, q = 0.f;
            for (int i = 0; i < 8; i++) { a += s1[i]; q += s2[i]; }
            s1[0] = 1.f / fmaxf(sqrtf(a), EPSv);
            g_q[j] = q;
        }
        __syncthreads();
        float inv = s1[0];
        for (int o = threadIdx.x; o < CH; o += 256) {
            size_t idx = (size_t)j * CH + o;
            s_Ekn[idx] = __float2half_rn(ek[o] * inv);
        }
    } else if (blk < Jn + Bn) {
        int b = blk - Jn;
        const float* kr = g_k + (size_t)b * CH;
        float ss = 0.f;
        for (int o = threadIdx.x; o < CH; o += 256) { float t = kr[o]; ss += t * t; }
#pragma unroll
        for (int off = 16; off; off >>= 1) ss += __shfl_xor_sync(0xffffffffu, ss, off);
        __shared__ float s1k[8];
        if (lane == 0) s1k[w] = ss;
        __syncthreads();
        if (threadIdx.x == 0) {
            float a = 0.f;
            for (int i = 0; i < 8; i++) a += s1k[i];
            g_ikn[b] = 1.f / fmaxf(sqrtf(a), EPSv);
        }
    } else {
        // EvT transpose-convert: tiles of 32x32, 256 threads (8 rows x 4 passes)
        int t = blk - Jn - Bn;            // 0 .. (Jn/32)*(CH/32)-1 = 671
        int tj = t % (Jn / 32);
        int tc = t / (Jn / 32);
        int j0 = tj * 32, c0 = tc * 32;
        __shared__ float tile[32][33];
        int tx = threadIdx.x & 31, ty = threadIdx.x >> 5;
#pragma unroll
        for (int rr = 0; rr < 4; rr++)
            tile[ty + rr * 8][tx] = g_Ev[(size_t)(j0 + ty + rr * 8) * CH + c0 + tx];
        __syncthreads();
#pragma unroll
        for (int rr = 0; rr < 4; rr++)
            s_EvT[(size_t)(c0 + ty + rr * 8) * Jn + j0 + tx] =
                __float2half_rn(tile[tx][ty + rr * 8]);
    }
}

// ---------------- attention (sums two cos split-K partials) ----------------
__global__ void attn_kernel(const float* __restrict__ bw) {
    int b = blockIdx.x;
    int m = threadIdx.x;
    int n = threadIdx.y;
    int j = n * Mn + m;
    float inv = g_ikn[b];
    size_t idx = (size_t)b * Jn + j;
    float c = (g_att[idx] + g_att[(size_t)Bn * Jn + idx]) * inv;

    float mx = c;
#pragma unroll
    for (int off = 16; off; off >>= 1) mx = fmaxf(mx, __shfl_xor_sync(0xffffffffu, mx, off));
    float e = __expf(c - mx);
    float s = e;
#pragma unroll
    for (int off = 16; off; off >>= 1) s += __shfl_xor_sync(0xffffffffu, s, off);
    float w = e / s;

    float lq = w * g_q[j];
#pragma unroll
    for (int off = 16; off; off >>= 1) lq += __shfl_xor_sync(0xffffffffu, lq, off);

    __shared__ float sl[NCLS];
    if (m == 0) sl[n] = lq + bw[0];
    __syncthreads();

    float fmx = -1e30f;
#pragma unroll
    for (int i = 0; i < NCLS; i++) fmx = fmaxf(fmx, sl[i]);
    float fs = 0.f;
#pragma unroll
    for (int i = 0; i < NCLS; i++) fs += __expf(sl[i] - fmx);
    float fw = __expf(sl[n] - fmx) / fs;

    s_att[idx] = __float2half_rn(fw * w);
}

// ---------------- output projection (8 rows/block, sums two fE partials) ----------------
__global__ void out_kernel(const float* __restrict__ Wout, const float* __restrict__ bout,
                           float* __restrict__ out) {
    __shared__ float sh[8][NCLS];
    int lane = threadIdx.x & 31, w = threadIdx.x >> 5;
    for (int bb = 0; bb < 8; bb++) {
        int b = blockIdx.x * 8 + bb;
        const float* vr  = g_v  + (size_t)b * CH;
        const float* fr0 = g_fE + (size_t)b * CH;
        const float* fr1 = g_fE + (size_t)Bn * CH + (size_t)b * CH;
        float acc[NCLS];
#pragma unroll
        for (int c = 0; c < NCLS; c++) acc[c] = 0.f;
        for (int o = threadIdx.x; o < CH; o += 256) {
            float rv = fmaxf(vr[o], 0.f);
            float rf = fmaxf(fr0[o] + fr1[o], 0.f);
#pragma unroll
            for (int c = 0; c < NCLS; c++)
                acc[c] += rv * Wout[(size_t)c * (2 * CH) + o] + rf * Wout[(size_t)c * (2 * CH) + CH + o];
        }
#pragma unroll
        for (int c = 0; c < NCLS; c++) {
            float vsum = acc[c];
#pragma unroll
            for (int off = 16; off; off >>= 1) vsum += __shfl_xor_sync(0xffffffffu, vsum, off);
            if (lane == 0) sh[w][c] = vsum;
        }
        __syncthreads();
        if (threadIdx.x < NCLS) {
            float s = 0.f;
            for (int wi = 0; wi < 8; wi++) s += sh[wi][threadIdx.x];
            out[(size_t)b * NCLS + threadIdx.x] = s + bout[threadIdx.x];
        }
        __syncthreads();
    }
}

// ---------------- host launcher ----------------
extern "C" void kernel_launch(void* const* d_in, const int* in_sizes, int n_in,
                              void* d_out, int out_size) {
    const float* x    = (const float*)d_in[0];
    const float* sf   = (const float*)d_in[1];
    const float* Wk   = (const float*)d_in[2];
    const float* bk   = (const float*)d_in[3];
    const float* Wv   = (const float*)d_in[4];
    const float* bv   = (const float*)d_in[5];
    const float* WEk  = (const float*)d_in[6];
    const float* bEk  = (const float*)d_in[7];
    const float* WEv  = (const float*)d_in[8];
    const float* bEv  = (const float*)d_in[9];
    const float* Ww   = (const float*)d_in[10];
    const float* bw   = (const float*)d_in[11];
    const float* Wout = (const float*)d_in[12];
    const float* bout = (const float*)d_in[13];
    float* out = (float*)d_out;

    h16 *xl, *sfT, *pWk, *pWv, *pWEk, *pWEv, *pk16, *Ekn, *att16, *EvT;
    float *p_Ek, *p_Ev, *p_k, *p_v, *p_att, *p_fE;
    cudaGetSymbolAddress((void**)&xl,   s_xl);
    cudaGetSymbolAddress((void**)&sfT,  s_sfT);
    cudaGetSymbolAddress((void**)&pWk,  s_Wk);
    cudaGetSymbolAddress((void**)&pWv,  s_Wv);
    cudaGetSymbolAddress((void**)&pWEk, s_WEk);
    cudaGetSymbolAddress((void**)&pWEv, s_WEv);
    cudaGetSymbolAddress((void**)&pk16, s_k);
    cudaGetSymbolAddress((void**)&Ekn,  s_Ekn);
    cudaGetSymbolAddress((void**)&att16, s_att);
    cudaGetSymbolAddress((void**)&EvT,  s_EvT);
    cudaGetSymbolAddress((void**)&p_Ek,  g_Ek);
    cudaGetSymbolAddress((void**)&p_Ev,  g_Ev);
    cudaGetSymbolAddress((void**)&p_k,   g_k);
    cudaGetSymbolAddress((void**)&p_v,   g_v);
    cudaGetSymbolAddress((void**)&p_att, g_att);
    cudaGetSymbolAddress((void**)&p_fE,  g_fE);

    static bool attr_done = false;
    if (!attr_done) {
        cudaFuncSetAttribute(front_gemm, cudaFuncAttributeMaxDynamicSharedMemorySize, GEMM_SMEM);
        cudaFuncSetAttribute(split_gemm, cudaFuncAttributeMaxDynamicSharedMemorySize, GEMM_SMEM);
        attr_done = true;
    }

    // 1) converters (2 launches)
    transpose_sf<<<dim3(CIN / 32, NCLS), dim3(32, 32)>>>(sf);
    convert_all<<<10240, 256>>>(Wk, Wv, WEk, WEv, x);

    // 2) fused front GEMMs: 352 CTAs
    {
        GP xk = {xl,  CIN, pWk,  CIN, bk,  p_k,  pk16,    CH, Bn, CH, CIN};
        GP xv = {xl,  CIN, pWv,  CIN, bv,  p_v,  nullptr, CH, Bn, CH, CIN};
        GP sk = {sfT, CIN, pWEk, CIN, bEk, p_Ek, nullptr, CH, Jn, CH, CIN};
        GP sv = {sfT, CIN, pWEv, CIN, bEv, p_Ev, nullptr, CH, Jn, CH, CIN};
        front_gemm<<<dim3(CH / 128, 22, 2), 256, GEMM_SMEM>>>(xk, xv, sk, sv);
    }

    // 3) merged prep: Ekn+q, knorm, EvT
    prep_evt<<<Jn + Bn + (Jn / 32) * (CH / 32), 256>>>(Ww);

    // 4) cos = k @ Ekn^T, split-K x2 (192 CTAs)
    {
        GP p0 = {pk16,       CH, Ekn,       CH, nullptr, p_att,              nullptr, Jn, Bn, Jn, 512};
        GP p1 = {pk16 + 512, CH, Ekn + 512, CH, nullptr, p_att + (size_t)Bn * Jn, nullptr, Jn, Bn, Jn, 512};
        split_gemm<<<dim3((Jn + 127) / 128, Bn / 128, 2), 256, GEMM_SMEM>>>(p0, p1);
    }

    // 5) softmaxes (sums partials)
    attn_kernel<<<Bn, dim3(32, NCLS)>>>(bw);

    // 6) fE = g @ EvT^T, split-K x2 (256 CTAs), K halves 336/336 (zero-fill tails)
    {
        GP p0 = {att16,       Jn, EvT,       Jn, nullptr, p_fE,                   nullptr, CH, Bn, CH, 336};
        GP p1 = {att16 + 336, Jn, EvT + 336, Jn, nullptr, p_fE + (size_t)Bn * CH, nullptr, CH, Bn, CH, 336};
        split_gemm<<<dim3(CH / 128, Bn / 128, 2), 256, GEMM_SMEM>>>(p0, p1);
    }

    // 7) output projection (sums fE partials)
    out_kernel<<<Bn / 8, 256>>>(Wout, bout, out);
}